// round 4
// baseline (speedup 1.0000x reference)
#include <cuda_runtime.h>
#include <math.h>

#define BATCH 65536
#define DD 512
#define HH 256
#define NBR 6
#define TM 64
#define MAX_TILES (BATCH / TM + NBR)
#define HS_LD 68   // padded stride for 64-row hidden tile (conflict-aware)

// ---------------- scratch (static __device__, no allocs) ----------------
__device__ float g_emb[(size_t)BATCH * DD];   // 128 MB: embedding + speed_in output
__device__ int g_idx[BATCH];                  // rows sorted by command bucket
__device__ int g_counts[NBR];
__device__ int g_cursor[NBR];
__device__ int g_tb[MAX_TILES], g_ts[MAX_TILES], g_tr[MAX_TILES];
__device__ int g_ntiles;

// ---------------- bucketing ----------------
__global__ void k_zero() {
    if (threadIdx.x < NBR) g_counts[threadIdx.x] = 0;
}

__global__ void k_hist(const int* __restrict__ cmd) {
    __shared__ int c[NBR];
    int t = threadIdx.x;
    if (t < NBR) c[t] = 0;
    __syncthreads();
    int r = blockIdx.x * blockDim.x + t;
    if (r < BATCH) atomicAdd(&c[cmd[r] - 1], 1);
    __syncthreads();
    if (t < NBR) atomicAdd(&g_counts[t], c[t]);
}

__global__ void k_plan() {
    int base = 0, nt = 0;
    for (int n = 0; n < NBR; n++) {
        int c = g_counts[n];
        g_cursor[n] = base;
        for (int off = 0; off < c; off += TM) {
            g_tb[nt] = n;
            g_ts[nt] = base + off;
            g_tr[nt] = (c - off < TM) ? (c - off) : TM;
            nt++;
        }
        base += c;
    }
    g_ntiles = nt;
}

__global__ void k_scatter(const int* __restrict__ cmd) {
    int r = blockIdx.x * blockDim.x + threadIdx.x;
    if (r < BATCH) {
        int p = atomicAdd(&g_cursor[cmd[r] - 1], 1);
        g_idx[p] = r;  // order-independent: each row's result lands at its own slot
    }
}

// ---------------- emb = embedding + relu(speed*sw1+sb1) @ sw2 + sb2 ----------------
// grid (BATCH/64, DD/128), 256 threads, 4x8 per thread, BK=8
__global__ __launch_bounds__(256) void k_emb(
    const float* __restrict__ embedding, const float* __restrict__ speed,
    const float* __restrict__ sw1, const float* __restrict__ sb1,
    const float* __restrict__ sw2, const float* __restrict__ sb2)
{
    __shared__ float As[8 * 64];
    __shared__ float Ws[8 * 128];
    __shared__ float sp[64];
    int tid = threadIdx.x;
    int row0 = blockIdx.x * 64;
    int col0 = blockIdx.y * 128;
    if (tid < 64) sp[tid] = speed[row0 + tid];

    int ry = tid & 15, cx = tid >> 4;
    float acc[4][8];
#pragma unroll
    for (int i = 0; i < 4; i++)
#pragma unroll
        for (int j = 0; j < 8; j++) acc[i][j] = 0.f;

    for (int kk = 0; kk < HH; kk += 8) {
        __syncthreads();  // covers sp on iter 0, prev compute afterwards
#pragma unroll
        for (int u = 0; u < 2; u++) {
            int idx = tid + u * 256;
            int k = idx >> 6, r = idx & 63;
            As[k * 64 + r] = fmaxf(fmaf(sp[r], sw1[kk + k], sb1[kk + k]), 0.f);
        }
        {
            int k = tid >> 5, c4 = tid & 31;
            *(float4*)&Ws[k * 128 + c4 * 4] =
                *(const float4*)&sw2[(size_t)(kk + k) * DD + col0 + c4 * 4];
        }
        __syncthreads();
#pragma unroll
        for (int k = 0; k < 8; k++) {
            float4 a = *(const float4*)&As[k * 64 + (ry << 2)];
            const float* wr = &Ws[k * 128 + (cx << 3)];
            float4 w0 = *(const float4*)wr;
            float4 w1v = *(const float4*)(wr + 4);
            float av[4] = {a.x, a.y, a.z, a.w};
            float wv[8] = {w0.x, w0.y, w0.z, w0.w, w1v.x, w1v.y, w1v.z, w1v.w};
#pragma unroll
            for (int i = 0; i < 4; i++)
#pragma unroll
                for (int j = 0; j < 8; j++)
                    acc[i][j] = fmaf(av[i], wv[j], acc[i][j]);
        }
    }

#pragma unroll
    for (int i = 0; i < 4; i++) {
        size_t r = (size_t)row0 + (ry << 2) + i;
#pragma unroll
        for (int h = 0; h < 2; h++) {
            int c = col0 + (cx << 3) + h * 4;
            float4 e = *(const float4*)&embedding[r * DD + c];
            float4 b = *(const float4*)&sb2[c];
            float4 o;
            o.x = acc[i][h * 4 + 0] + e.x + b.x;
            o.y = acc[i][h * 4 + 1] + e.y + b.y;
            o.z = acc[i][h * 4 + 2] + e.z + b.z;
            o.w = acc[i][h * 4 + 3] + e.w + b.w;
            *(float4*)&g_emb[r * DD + c] = o;
        }
    }
}

// ---------------- fused 3-layer MLP (per 64-row tile, branch-pure) ----------------
// layer1: [64,512] @ [512,256] -> relu -> smem (transposed)
// layer2: [64,256] @ [256,256] -> relu -> smem
// layer3: [64,256] @ [256,NOUT] (+sigmoid) -> scatter to out
template <int NOUT, bool SIG, bool GATHER>
__global__ __launch_bounds__(256, 2) void k_mlp3(
    const float* __restrict__ w1, const float* __restrict__ b1,
    const float* __restrict__ w2, const float* __restrict__ b2,
    const float* __restrict__ w3, const float* __restrict__ b3,
    float* __restrict__ out)
{
    extern __shared__ float sm[];
    float* As = sm;                              // 8*64
    float* Ws = sm + 512;                        // 8*256 (reused for w3)
    float* Hs = sm + 2560;                       // 256*HS_LD, layout [col][row]
    int* rid = (int*)(sm + 2560 + 256 * HS_LD);  // 64

    int tid = threadIdx.x;
    int nb, start, nrows;
    if (GATHER) {
        int t = blockIdx.x;
        if (t >= g_ntiles) return;
        nb = g_tb[t]; start = g_ts[t]; nrows = g_tr[t];
    } else {
        nb = 0; start = blockIdx.x * TM; nrows = TM;
    }
    const float* w1b = w1 + (size_t)nb * DD * HH;
    const float* w2b = w2 + (size_t)nb * HH * HH;
    const float* w3b = w3 + (size_t)nb * HH * NOUT;
    const float* b1b = b1 + nb * HH;
    const float* b2b = b2 + nb * HH;
    const float* b3b = b3 + nb * NOUT;

    if (tid < TM) {
        int i = (tid < nrows) ? tid : (nrows - 1);  // clamp pads (stores guarded later)
        rid[tid] = GATHER ? g_idx[start + i] : (start + i);
    }

    int ry = tid & 15, cx = tid >> 4;  // 4 rows x 16 cols per thread
    float acc[4][16];
#pragma unroll
    for (int i = 0; i < 4; i++)
#pragma unroll
        for (int j = 0; j < 16; j++) acc[i][j] = 0.f;

    // ---- layer 1: K = DD ----
    for (int kk = 0; kk < DD; kk += 8) {
        __syncthreads();  // covers rid on iter 0
        if (tid < 128) {
            int r = tid >> 1, v = tid & 1;
            float4 e = *(const float4*)&g_emb[(size_t)rid[r] * DD + kk + v * 4];
            As[(v * 4 + 0) * 64 + r] = e.x;
            As[(v * 4 + 1) * 64 + r] = e.y;
            As[(v * 4 + 2) * 64 + r] = e.z;
            As[(v * 4 + 3) * 64 + r] = e.w;
        }
#pragma unroll
        for (int u = 0; u < 2; u++) {
            int idx = tid + u * 256;
            int k = idx >> 6, c4 = idx & 63;
            *(float4*)&Ws[k * 256 + c4 * 4] =
                *(const float4*)&w1b[(size_t)(kk + k) * HH + c4 * 4];
        }
        __syncthreads();
#pragma unroll
        for (int k = 0; k < 8; k++) {
            float4 a = *(const float4*)&As[k * 64 + (ry << 2)];
            const float* wr = &Ws[k * 256 + (cx << 4)];
            float4 w0 = *(const float4*)wr;
            float4 wA = *(const float4*)(wr + 4);
            float4 wB = *(const float4*)(wr + 8);
            float4 wC = *(const float4*)(wr + 12);
            float av[4] = {a.x, a.y, a.z, a.w};
            float wv[16] = {w0.x, w0.y, w0.z, w0.w, wA.x, wA.y, wA.z, wA.w,
                            wB.x, wB.y, wB.z, wB.w, wC.x, wC.y, wC.z, wC.w};
#pragma unroll
            for (int i = 0; i < 4; i++)
#pragma unroll
                for (int j = 0; j < 16; j++)
                    acc[i][j] = fmaf(av[i], wv[j], acc[i][j]);
        }
    }
    __syncthreads();
    // h1 = relu(acc + b1) -> Hs[c][r]
#pragma unroll
    for (int j = 0; j < 16; j++) {
        int c = (cx << 4) + j;
        float bv = b1b[c];
#pragma unroll
        for (int i = 0; i < 4; i++)
            Hs[c * HS_LD + (ry << 2) + i] = fmaxf(acc[i][j] + bv, 0.f);
    }
#pragma unroll
    for (int i = 0; i < 4; i++)
#pragma unroll
        for (int j = 0; j < 16; j++) acc[i][j] = 0.f;

    // ---- layer 2: K = HH, A read straight from Hs ----
    for (int kk = 0; kk < HH; kk += 8) {
        __syncthreads();  // covers Hs writeback on iter 0
#pragma unroll
        for (int u = 0; u < 2; u++) {
            int idx = tid + u * 256;
            int k = idx >> 6, c4 = idx & 63;
            *(float4*)&Ws[k * 256 + c4 * 4] =
                *(const float4*)&w2b[(size_t)(kk + k) * HH + c4 * 4];
        }
        __syncthreads();
#pragma unroll
        for (int k = 0; k < 8; k++) {
            float4 a = *(const float4*)&Hs[(kk + k) * HS_LD + (ry << 2)];
            const float* wr = &Ws[k * 256 + (cx << 4)];
            float4 w0 = *(const float4*)wr;
            float4 wA = *(const float4*)(wr + 4);
            float4 wB = *(const float4*)(wr + 8);
            float4 wC = *(const float4*)(wr + 12);
            float av[4] = {a.x, a.y, a.z, a.w};
            float wv[16] = {w0.x, w0.y, w0.z, w0.w, wA.x, wA.y, wA.z, wA.w,
                            wB.x, wB.y, wB.z, wB.w, wC.x, wC.y, wC.z, wC.w};
#pragma unroll
            for (int i = 0; i < 4; i++)
#pragma unroll
                for (int j = 0; j < 16; j++)
                    acc[i][j] = fmaf(av[i], wv[j], acc[i][j]);
        }
    }
    __syncthreads();
    // h2 = relu(acc + b2) -> Hs[c][r]
#pragma unroll
    for (int j = 0; j < 16; j++) {
        int c = (cx << 4) + j;
        float bv = b2b[c];
#pragma unroll
        for (int i = 0; i < 4; i++)
            Hs[c * HS_LD + (ry << 2) + i] = fmaxf(acc[i][j] + bv, 0.f);
    }
    // stage w3 into Ws
    for (int idx = tid; idx < HH * NOUT; idx += 256) Ws[idx] = w3b[idx];
    __syncthreads();

    // ---- layer 3 epilogue: one thread per row ----
    if (tid < nrows) {
        float a3[NOUT];
#pragma unroll
        for (int o = 0; o < NOUT; o++) a3[o] = b3b[o];
#pragma unroll 8
        for (int k = 0; k < HH; k++) {
            float v = Hs[k * HS_LD + tid];
#pragma unroll
            for (int o = 0; o < NOUT; o++)
                a3[o] = fmaf(v, Ws[k * NOUT + o], a3[o]);
        }
        size_t orow = (size_t)(GATHER ? rid[tid] : (start + tid));
#pragma unroll
        for (int o = 0; o < NOUT; o++) {
            float v = a3[o];
            if (SIG) v = 1.f / (1.f + expf(-v));
            out[orow * NOUT + o] = v;
        }
    }
}

// ---------------- launch ----------------
extern "C" void kernel_launch(void* const* d_in, const int* in_sizes, int n_in,
                              void* d_out, int out_size)
{
    const float* embedding = (const float*)d_in[0];
    const float* speed     = (const float*)d_in[1];
    const int*   command   = (const int*)d_in[2];
    const float* sw1 = (const float*)d_in[3];
    const float* sb1 = (const float*)d_in[4];
    const float* sw2 = (const float*)d_in[5];
    const float* sb2 = (const float*)d_in[6];
    const float* bw1 = (const float*)d_in[7];
    const float* bb1 = (const float*)d_in[8];
    const float* bw2 = (const float*)d_in[9];
    const float* bb2 = (const float*)d_in[10];
    const float* bw3 = (const float*)d_in[11];
    const float* bb3 = (const float*)d_in[12];
    const float* ow1 = (const float*)d_in[13];
    const float* ob1 = (const float*)d_in[14];
    const float* ow2 = (const float*)d_in[15];
    const float* ob2 = (const float*)d_in[16];
    const float* ow3 = (const float*)d_in[17];
    const float* ob3 = (const float*)d_in[18];
    float* out = (float*)d_out;

    const int SMEM = (2560 + 256 * HS_LD) * 4 + TM * 4;  // 80128 B
    cudaFuncSetAttribute((const void*)k_mlp3<3, true, true>,
                         cudaFuncAttributeMaxDynamicSharedMemorySize, SMEM);
    cudaFuncSetAttribute((const void*)k_mlp3<1, false, false>,
                         cudaFuncAttributeMaxDynamicSharedMemorySize, SMEM);

    k_zero<<<1, 32>>>();
    k_hist<<<BATCH / 256, 256>>>(command);
    k_plan<<<1, 1>>>();
    k_scatter<<<BATCH / 256, 256>>>(command);
    k_emb<<<dim3(BATCH / 64, DD / 128), 256>>>(embedding, speed, sw1, sb1, sw2, sb2);
    // branches: only the selected branch per row (mask-equivalent), branch-pure tiles
    k_mlp3<3, true, true><<<MAX_TILES, 256, SMEM>>>(bw1, bb1, bw2, bb2, bw3, bb3, out);
    // speed head: dense over all rows
    k_mlp3<1, false, false><<<BATCH / TM, 256, SMEM>>>(ow1, ob1, ow2, ob2, ow3, ob3,
                                                       out + (size_t)3 * BATCH);
}

// round 5
// speedup vs baseline: 2.2739x; 2.2739x over previous
#include <cuda_runtime.h>
#include <math.h>

#define BATCH 65536
#define DD 512
#define HH 256
#define NBR 6
#define TM 128
#define MAX_TILES (BATCH / TM + NBR)

// smem layout pads (bank-conflict-free fragment addressing)
#define LDA 36    // A-stage stride: bank=(4r+k)%32 -> permutation over warp
#define LDH 260   // Hs stride:      bank=(4r+k)%32 -> permutation
#define LDW 264   // W-stage (mlp):  bank=(8k+n)%32 -> permutation
#define LDW2 136  // W-stage (emb):  bank=(8k+n)%32 -> permutation

// ---------------- scratch (static __device__, no allocs) ----------------
__device__ float g_emb[(size_t)BATCH * DD];
__device__ int g_idx[BATCH];
__device__ int g_counts[NBR];
__device__ int g_cursor[NBR];
__device__ int g_tb[MAX_TILES], g_ts[MAX_TILES], g_tr[MAX_TILES];
__device__ int g_ntiles;

// ---------------- helpers ----------------
__device__ __forceinline__ unsigned f2tf(float f) {
    unsigned r;
    asm("cvt.rn.tf32.f32 %0, %1;" : "=r"(r) : "f"(f));
    return r;
}

__device__ __forceinline__ void mma_tf32(float* d, const unsigned* a, const unsigned* b) {
    asm volatile(
        "mma.sync.aligned.m16n8k8.row.col.f32.tf32.tf32.f32 "
        "{%0,%1,%2,%3},{%4,%5,%6,%7},{%8,%9},{%0,%1,%2,%3};"
        : "+f"(d[0]), "+f"(d[1]), "+f"(d[2]), "+f"(d[3])
        : "r"(a[0]), "r"(a[1]), "r"(a[2]), "r"(a[3]), "r"(b[0]), "r"(b[1]));
}

// ---------------- bucketing ----------------
__global__ void k_zero() {
    if (threadIdx.x < NBR) g_counts[threadIdx.x] = 0;
}

__global__ void k_hist(const int* __restrict__ cmd) {
    __shared__ int c[NBR];
    int t = threadIdx.x;
    if (t < NBR) c[t] = 0;
    __syncthreads();
    int r = blockIdx.x * blockDim.x + t;
    if (r < BATCH) atomicAdd(&c[cmd[r] - 1], 1);
    __syncthreads();
    if (t < NBR) atomicAdd(&g_counts[t], c[t]);
}

__global__ void k_plan() {
    int base = 0, nt = 0;
    for (int n = 0; n < NBR; n++) {
        int c = g_counts[n];
        g_cursor[n] = base;
        for (int off = 0; off < c; off += TM) {
            g_tb[nt] = n;
            g_ts[nt] = base + off;
            g_tr[nt] = (c - off < TM) ? (c - off) : TM;
            nt++;
        }
        base += c;
    }
    g_ntiles = nt;
}

__global__ void k_scatter(const int* __restrict__ cmd) {
    int r = blockIdx.x * blockDim.x + threadIdx.x;
    if (r < BATCH) {
        int p = atomicAdd(&g_cursor[cmd[r] - 1], 1);
        g_idx[p] = r;  // order-independent: each row's result computed identically
    }
}

// ---------------- emb = embedding + relu(speed*sw1+sb1) @ sw2 + sb2 ----------------
// block: 128 rows x 128 cols, 256 threads (8 warps, 4x2), warp tile 32x64 via tf32 mma
__global__ __launch_bounds__(256) void k_emb(
    const float* __restrict__ embedding, const float* __restrict__ speed,
    const float* __restrict__ sw1, const float* __restrict__ sb1,
    const float* __restrict__ sw2, const float* __restrict__ sb2)
{
    __shared__ float Sp[128];
    __shared__ unsigned As[128 * LDA];
    __shared__ unsigned Ws[32 * LDW2];

    int tid = threadIdx.x;
    int lane = tid & 31, w = tid >> 5;
    int wm = w & 3, wn = w >> 2;
    int row0 = blockIdx.x * 128;
    int col0 = blockIdx.y * 128;

    if (tid < 128) Sp[tid] = speed[row0 + tid];
    __syncthreads();

    float acc[2][8][4];
#pragma unroll
    for (int i = 0; i < 2; i++)
#pragma unroll
        for (int j = 0; j < 8; j++)
#pragma unroll
            for (int q = 0; q < 4; q++) acc[i][j][q] = 0.f;

    for (int kc = 0; kc < HH / 32; kc++) {
        int k0 = kc * 32;
        // stage A = relu(speed*sw1+sb1): thread's h = lane (fixed per chunk)
        {
            float w1v = sw1[k0 + lane];
            float b1v = sb1[k0 + lane];
#pragma unroll
            for (int u = 0; u < 16; u++) {
                int r = u * 8 + w;
                float v = fmaxf(fmaf(Sp[r], w1v, b1v), 0.f);
                As[r * LDA + lane] = f2tf(v);
            }
        }
        // stage W = sw2 chunk [32 k][128 cols]
#pragma unroll
        for (int u = 0; u < 4; u++) {
            int idx = u * 256 + tid;
            int k = idx >> 5, q = idx & 31;
            float4 v = *(const float4*)&sw2[(size_t)(k0 + k) * DD + col0 + q * 4];
            unsigned* dst = &Ws[k * LDW2 + q * 4];
            dst[0] = f2tf(v.x); dst[1] = f2tf(v.y);
            dst[2] = f2tf(v.z); dst[3] = f2tf(v.w);
        }
        __syncthreads();
#pragma unroll
        for (int ks = 0; ks < 4; ks++) {
            int kk = ks * 8;
            unsigned a[2][4], b[8][2];
#pragma unroll
            for (int mi = 0; mi < 2; mi++) {
                int r = wm * 32 + mi * 16 + (lane >> 2);
                int c = kk + (lane & 3);
                a[mi][0] = As[r * LDA + c];
                a[mi][1] = As[(r + 8) * LDA + c];
                a[mi][2] = As[r * LDA + c + 4];
                a[mi][3] = As[(r + 8) * LDA + c + 4];
            }
#pragma unroll
            for (int ni = 0; ni < 8; ni++) {
                int n = wn * 64 + ni * 8 + (lane >> 2);
                b[ni][0] = Ws[(kk + (lane & 3)) * LDW2 + n];
                b[ni][1] = Ws[(kk + (lane & 3) + 4) * LDW2 + n];
            }
#pragma unroll
            for (int mi = 0; mi < 2; mi++)
#pragma unroll
                for (int ni = 0; ni < 8; ni++) mma_tf32(acc[mi][ni], a[mi], b[ni]);
        }
        __syncthreads();
    }

    // epilogue: + embedding + sb2 -> g_emb
#pragma unroll
    for (int mi = 0; mi < 2; mi++) {
        int r = row0 + wm * 32 + mi * 16 + (lane >> 2);
#pragma unroll
        for (int ni = 0; ni < 8; ni++) {
            int n = col0 + wn * 64 + ni * 8 + 2 * (lane & 3);
            float s0 = sb2[n], s1 = sb2[n + 1];
            {
                size_t idx = (size_t)r * DD + n;
                float2 e = *(const float2*)&embedding[idx];
                float2 o = {acc[mi][ni][0] + e.x + s0, acc[mi][ni][1] + e.y + s1};
                *(float2*)&g_emb[idx] = o;
            }
            {
                size_t idx = (size_t)(r + 8) * DD + n;
                float2 e = *(const float2*)&embedding[idx];
                float2 o = {acc[mi][ni][2] + e.x + s0, acc[mi][ni][3] + e.y + s1};
                *(float2*)&g_emb[idx] = o;
            }
        }
    }
}

// ---------------- fused 3-layer MLP on tensor cores ----------------
// 128-row tile, 512 threads (16 warps, 4x4), warp tile 32x64.
// L1: [128,512]@[512,256] (K-chunked), L2: [128,256]@[256,256] (Hs resident),
// L3: [128,256]@[256,NOUT] scalar epilogue (+sigmoid) with scattered stores.
template <int NOUT, bool SIG, bool GATHER>
__global__ __launch_bounds__(512, 1) void k_mlp3(
    const float* __restrict__ w1, const float* __restrict__ b1,
    const float* __restrict__ w2, const float* __restrict__ b2,
    const float* __restrict__ w3, const float* __restrict__ b3,
    float* __restrict__ out)
{
    extern __shared__ float smf[];
    float* Hs = smf;                                   // 128*LDH
    unsigned* Ws = (unsigned*)(smf + 128 * LDH);       // 32*LDW
    unsigned* As = Ws + 32 * LDW;                      // 128*LDA
    int* rid = (int*)(As + 128 * LDA);                 // 128

    int tid = threadIdx.x;
    int lane = tid & 31, w = tid >> 5;
    int wm = w & 3, wn = w >> 2;

    int nb, start, nrows;
    if (GATHER) {
        int t = blockIdx.x;
        if (t >= g_ntiles) return;
        nb = g_tb[t]; start = g_ts[t]; nrows = g_tr[t];
    } else {
        nb = 0; start = blockIdx.x * TM; nrows = TM;
    }
    const float* w1b = w1 + (size_t)nb * DD * HH;
    const float* w2b = w2 + (size_t)nb * HH * HH;
    const float* w3b = w3 + (size_t)nb * HH * NOUT;
    const float* b1b = b1 + nb * HH;
    const float* b2b = b2 + nb * HH;
    const float* b3b = b3 + nb * NOUT;

    if (tid < TM) {
        int i = (tid < nrows) ? tid : (nrows - 1);  // clamp pads; stores guarded
        rid[tid] = GATHER ? g_idx[start + i] : (start + i);
    }
    __syncthreads();

    float acc[2][8][4];
#pragma unroll
    for (int i = 0; i < 2; i++)
#pragma unroll
        for (int j = 0; j < 8; j++)
#pragma unroll
            for (int q = 0; q < 4; q++) acc[i][j][q] = 0.f;

    // ---- layer 1: K = 512 in 16 chunks of 32 ----
    for (int kc = 0; kc < DD / 32; kc++) {
        int k0 = kc * 32;
        // stage A: gathered emb rows [128, 32]
#pragma unroll
        for (int u = 0; u < 2; u++) {
            int idx = u * 512 + tid;
            int r = idx >> 3, q = idx & 7;
            float4 v = *(const float4*)&g_emb[(size_t)rid[r] * DD + k0 + q * 4];
            unsigned* dst = &As[r * LDA + q * 4];
            dst[0] = f2tf(v.x); dst[1] = f2tf(v.y);
            dst[2] = f2tf(v.z); dst[3] = f2tf(v.w);
        }
        // stage W1 chunk [32 k, 256 n]
#pragma unroll
        for (int u = 0; u < 4; u++) {
            int idx = u * 512 + tid;
            int k = idx >> 6, q = idx & 63;
            float4 v = *(const float4*)&w1b[(size_t)(k0 + k) * HH + q * 4];
            unsigned* dst = &Ws[k * LDW + q * 4];
            dst[0] = f2tf(v.x); dst[1] = f2tf(v.y);
            dst[2] = f2tf(v.z); dst[3] = f2tf(v.w);
        }
        __syncthreads();
#pragma unroll
        for (int ks = 0; ks < 4; ks++) {
            int kk = ks * 8;
            unsigned a[2][4], b[8][2];
#pragma unroll
            for (int mi = 0; mi < 2; mi++) {
                int r = wm * 32 + mi * 16 + (lane >> 2);
                int c = kk + (lane & 3);
                a[mi][0] = As[r * LDA + c];
                a[mi][1] = As[(r + 8) * LDA + c];
                a[mi][2] = As[r * LDA + c + 4];
                a[mi][3] = As[(r + 8) * LDA + c + 4];
            }
#pragma unroll
            for (int ni = 0; ni < 8; ni++) {
                int n = wn * 64 + ni * 8 + (lane >> 2);
                b[ni][0] = Ws[(kk + (lane & 3)) * LDW + n];
                b[ni][1] = Ws[(kk + (lane & 3) + 4) * LDW + n];
            }
#pragma unroll
            for (int mi = 0; mi < 2; mi++)
#pragma unroll
                for (int ni = 0; ni < 8; ni++) mma_tf32(acc[mi][ni], a[mi], b[ni]);
        }
        __syncthreads();
    }

    // h1 = relu(acc + b1) -> Hs (tf32-rounded), reset acc
#pragma unroll
    for (int mi = 0; mi < 2; mi++) {
        int r = wm * 32 + mi * 16 + (lane >> 2);
#pragma unroll
        for (int ni = 0; ni < 8; ni++) {
            int n = wn * 64 + ni * 8 + 2 * (lane & 3);
            float bb0 = b1b[n], bb1 = b1b[n + 1];
            Hs[r * LDH + n]           = __uint_as_float(f2tf(fmaxf(acc[mi][ni][0] + bb0, 0.f)));
            Hs[r * LDH + n + 1]       = __uint_as_float(f2tf(fmaxf(acc[mi][ni][1] + bb1, 0.f)));
            Hs[(r + 8) * LDH + n]     = __uint_as_float(f2tf(fmaxf(acc[mi][ni][2] + bb0, 0.f)));
            Hs[(r + 8) * LDH + n + 1] = __uint_as_float(f2tf(fmaxf(acc[mi][ni][3] + bb1, 0.f)));
#pragma unroll
            for (int q = 0; q < 4; q++) acc[mi][ni][q] = 0.f;
        }
    }
    __syncthreads();

    // ---- layer 2: K = 256, A = Hs resident; only W chunked ----
    const unsigned* Hu = (const unsigned*)Hs;
    for (int kc = 0; kc < HH / 32; kc++) {
        int k0 = kc * 32;
#pragma unroll
        for (int u = 0; u < 4; u++) {
            int idx = u * 512 + tid;
            int k = idx >> 6, q = idx & 63;
            float4 v = *(const float4*)&w2b[(size_t)(k0 + k) * HH + q * 4];
            unsigned* dst = &Ws[k * LDW + q * 4];
            dst[0] = f2tf(v.x); dst[1] = f2tf(v.y);
            dst[2] = f2tf(v.z); dst[3] = f2tf(v.w);
        }
        __syncthreads();
#pragma unroll
        for (int ks = 0; ks < 4; ks++) {
            int kk = ks * 8;
            int kg = k0 + kk;
            unsigned a[2][4], b[8][2];
#pragma unroll
            for (int mi = 0; mi < 2; mi++) {
                int r = wm * 32 + mi * 16 + (lane >> 2);
                int c = kg + (lane & 3);
                a[mi][0] = Hu[r * LDH + c];
                a[mi][1] = Hu[(r + 8) * LDH + c];
                a[mi][2] = Hu[r * LDH + c + 4];
                a[mi][3] = Hu[(r + 8) * LDH + c + 4];
            }
#pragma unroll
            for (int ni = 0; ni < 8; ni++) {
                int n = wn * 64 + ni * 8 + (lane >> 2);
                b[ni][0] = Ws[(kk + (lane & 3)) * LDW + n];
                b[ni][1] = Ws[(kk + (lane & 3) + 4) * LDW + n];
            }
#pragma unroll
            for (int mi = 0; mi < 2; mi++)
#pragma unroll
                for (int ni = 0; ni < 8; ni++) mma_tf32(acc[mi][ni], a[mi], b[ni]);
        }
        __syncthreads();  // also protects Hs before h2 overwrite on last iter
    }

    // h2 = relu(acc + b2) -> Hs
#pragma unroll
    for (int mi = 0; mi < 2; mi++) {
        int r = wm * 32 + mi * 16 + (lane >> 2);
#pragma unroll
        for (int ni = 0; ni < 8; ni++) {
            int n = wn * 64 + ni * 8 + 2 * (lane & 3);
            float bb0 = b2b[n], bb1 = b2b[n + 1];
            Hs[r * LDH + n]           = fmaxf(acc[mi][ni][0] + bb0, 0.f);
            Hs[r * LDH + n + 1]       = fmaxf(acc[mi][ni][1] + bb1, 0.f);
            Hs[(r + 8) * LDH + n]     = fmaxf(acc[mi][ni][2] + bb0, 0.f);
            Hs[(r + 8) * LDH + n + 1] = fmaxf(acc[mi][ni][3] + bb1, 0.f);
        }
    }
    // stage w3 (fp32) into As region
    float* W3s = (float*)As;
    for (int idx = tid; idx < HH * NOUT; idx += 512) W3s[idx] = w3b[idx];
    __syncthreads();

    // ---- layer 3 epilogue: one thread per row (fp32 scalar) ----
    if (tid < nrows) {
        float a3[NOUT];
#pragma unroll
        for (int o = 0; o < NOUT; o++) a3[o] = b3b[o];
#pragma unroll 8
        for (int k = 0; k < HH; k++) {
            float v = Hs[tid * LDH + k];
#pragma unroll
            for (int o = 0; o < NOUT; o++)
                a3[o] = fmaf(v, W3s[k * NOUT + o], a3[o]);
        }
        size_t orow = (size_t)(GATHER ? rid[tid] : (start + tid));
#pragma unroll
        for (int o = 0; o < NOUT; o++) {
            float v = a3[o];
            if (SIG) v = 1.f / (1.f + expf(-v));
            out[orow * NOUT + o] = v;
        }
    }
}

// ---------------- launch ----------------
extern "C" void kernel_launch(void* const* d_in, const int* in_sizes, int n_in,
                              void* d_out, int out_size)
{
    const float* embedding = (const float*)d_in[0];
    const float* speed     = (const float*)d_in[1];
    const int*   command   = (const int*)d_in[2];
    const float* sw1 = (const float*)d_in[3];
    const float* sb1 = (const float*)d_in[4];
    const float* sw2 = (const float*)d_in[5];
    const float* sb2 = (const float*)d_in[6];
    const float* bw1 = (const float*)d_in[7];
    const float* bb1 = (const float*)d_in[8];
    const float* bw2 = (const float*)d_in[9];
    const float* bb2 = (const float*)d_in[10];
    const float* bw3 = (const float*)d_in[11];
    const float* bb3 = (const float*)d_in[12];
    const float* ow1 = (const float*)d_in[13];
    const float* ob1 = (const float*)d_in[14];
    const float* ow2 = (const float*)d_in[15];
    const float* ob2 = (const float*)d_in[16];
    const float* ow3 = (const float*)d_in[17];
    const float* ob3 = (const float*)d_in[18];
    float* out = (float*)d_out;

    const int SMEM = (128 * LDH + 32 * LDW + 128 * LDA + 128) * 4;  // 185,856 B
    cudaFuncSetAttribute((const void*)k_mlp3<3, true, true>,
                         cudaFuncAttributeMaxDynamicSharedMemorySize, SMEM);
    cudaFuncSetAttribute((const void*)k_mlp3<1, false, false>,
                         cudaFuncAttributeMaxDynamicSharedMemorySize, SMEM);

    k_zero<<<1, 32>>>();
    k_hist<<<BATCH / 256, 256>>>(command);
    k_plan<<<1, 1>>>();
    k_scatter<<<BATCH / 256, 256>>>(command);
    k_emb<<<dim3(BATCH / 128, DD / 128), 256>>>(embedding, speed, sw1, sb1, sw2, sb2);
    // branch heads: only the selected branch per row, branch-pure 128-row tiles
    k_mlp3<3, true, true><<<MAX_TILES, 512, SMEM>>>(bw1, bb1, bw2, bb2, bw3, bb3, out);
    // speed head: dense
    k_mlp3<1, false, false><<<BATCH / TM, 512, SMEM>>>(ow1, ob1, ow2, ob2, ow3, ob3,
                                                       out + (size_t)3 * BATCH);
}

// round 6
// speedup vs baseline: 3.2014x; 1.4079x over previous
#include <cuda_runtime.h>
#include <math.h>

#define BATCH 65536
#define DD 512
#define HH 256
#define NBR 6
#define TM 128
#define MAX_TILES (BATCH / TM + NBR)   // 518

// tf32 weight scratch offsets (in unsigned elements)
#define OFF_SW2 0
#define OFF_BW1 131072
#define OFF_BW2 917504
#define OFF_OW1 1310720
#define OFF_OW2 1441792
#define WT_TOTAL 1507328

// ---------------- scratch (static __device__, no allocs) ----------------
__device__ float g_emb[(size_t)BATCH * DD];   // holds tf32 BIT PATTERNS of emb
__device__ unsigned g_wt[WT_TOTAL];           // pre-rounded tf32 weights
__device__ int g_idx[BATCH];
__device__ int g_counts[NBR];
__device__ int g_cursor[NBR];
__device__ int g_tb[MAX_TILES], g_ts[MAX_TILES], g_tr[MAX_TILES];
__device__ int g_ntiles;

// ---------------- helpers ----------------
__device__ __forceinline__ unsigned f2tf(float f) {
    unsigned r;
    asm("cvt.rn.tf32.f32 %0, %1;" : "=r"(r) : "f"(f));
    return r;
}

__device__ __forceinline__ void mma_tf32(float* d, const unsigned* a, const unsigned* b) {
    asm volatile(
        "mma.sync.aligned.m16n8k8.row.col.f32.tf32.tf32.f32 "
        "{%0,%1,%2,%3},{%4,%5,%6,%7},{%8,%9},{%0,%1,%2,%3};"
        : "+f"(d[0]), "+f"(d[1]), "+f"(d[2]), "+f"(d[3])
        : "r"(a[0]), "r"(a[1]), "r"(a[2]), "r"(a[3]), "r"(b[0]), "r"(b[1]));
}

__device__ __forceinline__ void cpa16(unsigned dst, const void* src) {
    asm volatile("cp.async.cg.shared.global [%0], [%1], 16;" :: "r"(dst), "l"(src) : "memory");
}
#define CP_COMMIT() asm volatile("cp.async.commit_group;" ::: "memory")
#define CP_WAIT0()  asm volatile("cp.async.wait_group 0;" ::: "memory")
#define CP_WAIT1()  asm volatile("cp.async.wait_group 1;" ::: "memory")

// One K=32 chunk of mma for a 128x256 block (16 warps, warp tile 32x64).
// A: stride LDAe; SWZ -> columns XOR-swizzled by 4*(r&7). W: stride 256, swizzled by 8*(k&3).
template <int LDAe, bool SWZ>
__device__ __forceinline__ void mma_chunk(const unsigned* __restrict__ A,
                                          const unsigned* __restrict__ W,
                                          int cbase, int lane, int wm, int wn,
                                          float acc[2][8][4]) {
    int swa = (lane >> 2) * 4;
    int swb = (lane & 3) * 8;
#pragma unroll
    for (int ks = 0; ks < 4; ks++) {
        int kk = ks * 8;
        unsigned a[2][4], b[8][2];
#pragma unroll
        for (int mi = 0; mi < 2; mi++) {
            int r = wm * 32 + mi * 16 + (lane >> 2);
            int c = cbase + kk + (lane & 3);
            int c1 = SWZ ? (c ^ swa) : c;
            int c2 = SWZ ? ((c + 4) ^ swa) : (c + 4);
            a[mi][0] = A[r * LDAe + c1];
            a[mi][1] = A[(r + 8) * LDAe + c1];
            a[mi][2] = A[r * LDAe + c2];
            a[mi][3] = A[(r + 8) * LDAe + c2];
        }
#pragma unroll
        for (int ni = 0; ni < 8; ni++) {
            int n = (wn * 64 + ni * 8 + (lane >> 2)) ^ swb;
            int k = kk + (lane & 3);
            b[ni][0] = W[k * 256 + n];
            b[ni][1] = W[(k + 4) * 256 + n];
        }
#pragma unroll
        for (int mi = 0; mi < 2; mi++)
#pragma unroll
            for (int ni = 0; ni < 8; ni++) mma_tf32(acc[mi][ni], a[mi], b[ni]);
    }
}

// ---------------- setup: weight pre-conversion + counts zero ----------------
__global__ void k_cvtw(const float* __restrict__ sw2, const float* __restrict__ bw1,
                       const float* __restrict__ bw2, const float* __restrict__ ow1,
                       const float* __restrict__ ow2) {
    int i = blockIdx.x * 256 + threadIdx.x;  // float4 index, total 376832
    const float* src;
    int base;
    if (i < 32768)       { src = sw2; base = 0; }
    else if (i < 229376) { src = bw1; base = 32768; }
    else if (i < 327680) { src = bw2; base = 229376; }
    else if (i < 360448) { src = ow1; base = 327680; }
    else                 { src = ow2; base = 360448; }
    float4 v = ((const float4*)src)[i - base];
    uint4 o = {f2tf(v.x), f2tf(v.y), f2tf(v.z), f2tf(v.w)};
    ((uint4*)g_wt)[i] = o;
    if (blockIdx.x == 0 && threadIdx.x < NBR) g_counts[threadIdx.x] = 0;
}

// ---------------- bucketing ----------------
__global__ void k_hist(const int* __restrict__ cmd) {
    __shared__ int c[NBR];
    int t = threadIdx.x;
    if (t < NBR) c[t] = 0;
    __syncthreads();
    atomicAdd(&c[cmd[blockIdx.x * 256 + t] - 1], 1);
    __syncthreads();
    if (t < NBR) atomicAdd(&g_counts[t], c[t]);
}

__global__ void k_plan() {
    int l = threadIdx.x;
    int c[NBR], base[NBR], tp[NBR];
    int b = 0, t = 0;
#pragma unroll
    for (int n = 0; n < NBR; n++) {
        c[n] = g_counts[n]; base[n] = b; tp[n] = t;
        b += c[n]; t += (c[n] + TM - 1) / TM;
    }
    for (int tile = l; tile < t; tile += 32) {
        int n = 0;
        while (n < NBR - 1 && tile >= tp[n + 1]) n++;
        int loc = tile - tp[n];
        g_tb[tile] = n;
        g_ts[tile] = base[n] + loc * TM;
        int rem = c[n] - loc * TM;
        g_tr[tile] = rem < TM ? rem : TM;
    }
    if (l == 0) g_ntiles = t;
    if (l < NBR) g_cursor[l] = base[l];
}

__global__ void k_scatter(const int* __restrict__ cmd) {
    __shared__ int lc[NBR], lb[NBR];
    int t = threadIdx.x;
    if (t < NBR) lc[t] = 0;
    __syncthreads();
    int r = blockIdx.x * 256 + t;
    int b = cmd[r] - 1;
    int rank = atomicAdd(&lc[b], 1);
    __syncthreads();
    if (t < NBR) lb[t] = atomicAdd(&g_cursor[t], lc[t]);
    __syncthreads();
    g_idx[lb[b] + rank] = r;  // per-row math downstream independent of permutation
}

// ---------------- emb = tf32(embedding + relu(speed*sw1+sb1) @ sw2 + sb2) ----------------
// block 128 rows x 256 cols, 512 threads, K=HH chunked by 32, W double-buffered cp.async
__global__ __launch_bounds__(512, 1) void k_emb(
    const float* __restrict__ embedding, const float* __restrict__ speed,
    const float* __restrict__ sw1, const float* __restrict__ sb1,
    const float* __restrict__ sb2) {
    extern __shared__ float smf[];
    unsigned* Asf = (unsigned*)smf;        // 128*256 swizzled, full K
    unsigned* Wsm = Asf + 32768;           // 2 x 32*256 swizzled
    float* sw1s = (float*)(Wsm + 16384);   // 256
    float* sb1s = sw1s + 256;              // 256
    float* Sp = sb1s + 256;                // 128

    int tid = threadIdx.x, lane = tid & 31, w = tid >> 5;
    int wm = w & 3, wn = w >> 2;
    int row0 = blockIdx.x * 128, col0 = blockIdx.y * 256;

    if (tid < 128) Sp[tid] = speed[row0 + tid];
    if (tid < 256) { sw1s[tid] = sw1[tid]; sb1s[tid] = sb1[tid]; }
    __syncthreads();

    for (int u = 0; u < 64; u++) {
        int idx = u * 512 + tid;
        int r = idx >> 8, c = idx & 255;
        float v = fmaxf(fmaf(Sp[r], sw1s[c], sb1s[c]), 0.f);
        Asf[r * 256 + (c ^ ((r & 7) * 4))] = f2tf(v);
    }

    unsigned aW = (unsigned)__cvta_generic_to_shared(Wsm);
    const unsigned* wt = g_wt + OFF_SW2;

    float acc[2][8][4];
#pragma unroll
    for (int i = 0; i < 2; i++)
#pragma unroll
        for (int j = 0; j < 8; j++)
#pragma unroll
            for (int q = 0; q < 4; q++) acc[i][j][q] = 0.f;

    // stage W chunk kc into buf
    auto stage = [&](int kc, int buf) {
#pragma unroll
        for (int u = 0; u < 4; u++) {
            int idx = u * 512 + tid;
            int k = idx >> 6, q = idx & 63;
            cpa16(aW + (unsigned)(buf * 8192 + k * 256 + ((q * 4) ^ ((k & 3) * 8))) * 4u,
                  wt + (size_t)(kc * 32 + k) * DD + col0 + q * 4);
        }
    };

    stage(0, 0); CP_COMMIT();
    for (int kc = 0; kc < 8; kc++) {
        if (kc < 7) { stage(kc + 1, (kc + 1) & 1); CP_COMMIT(); CP_WAIT1(); }
        else CP_WAIT0();
        __syncthreads();
        mma_chunk<256, true>(Asf, Wsm + (kc & 1) * 8192, kc * 32, lane, wm, wn, acc);
        __syncthreads();
    }

    unsigned* gE = (unsigned*)g_emb;
#pragma unroll
    for (int mi = 0; mi < 2; mi++) {
        int r = row0 + wm * 32 + mi * 16 + (lane >> 2);
#pragma unroll
        for (int ni = 0; ni < 8; ni++) {
            int n = col0 + wn * 64 + ni * 8 + 2 * (lane & 3);
            float s0 = sb2[n], s1 = sb2[n + 1];
            {
                size_t ix = (size_t)r * DD + n;
                float2 e = *(const float2*)&embedding[ix];
                uint2 o = {f2tf(acc[mi][ni][0] + e.x + s0), f2tf(acc[mi][ni][1] + e.y + s1)};
                *(uint2*)&gE[ix] = o;
            }
            {
                size_t ix = (size_t)(r + 8) * DD + n;
                float2 e = *(const float2*)&embedding[ix];
                uint2 o = {f2tf(acc[mi][ni][2] + e.x + s0), f2tf(acc[mi][ni][3] + e.y + s1)};
                *(uint2*)&gE[ix] = o;
            }
        }
    }
}

// ---------------- fused 3-layer MLP, both heads in one launch ----------------
// bid < MAX_TILES: branch-pure gathered tile (NOUT=3, sigmoid); else speed head tile.
__global__ __launch_bounds__(512, 1) void k_mlp_all(
    const float* __restrict__ bb1, const float* __restrict__ bb2,
    const float* __restrict__ bw3, const float* __restrict__ bb3,
    const float* __restrict__ ob1, const float* __restrict__ ob2,
    const float* __restrict__ ow3, const float* __restrict__ ob3,
    float* __restrict__ out) {
    extern __shared__ float smf[];
    float* Hs = smf;                              // 128*260 (padded, conflict-free)
    unsigned* Wsm = (unsigned*)(smf + 33280);     // 2 x 32*256 swizzled
    unsigned* Asm = Wsm + 16384;                  // 2 x 128*32 swizzled
    int* rid = (int*)(Asm + 8192);                // 128

    int tid = threadIdx.x, lane = tid & 31, w = tid >> 5;
    int wm = w & 3, wn = w >> 2;
    int bid = blockIdx.x;

    const unsigned *w1t, *w2t;
    const float *w3, *b1, *b2, *b3;
    float* obase;
    int nout, start, nrows;
    bool sig, gather;
    if (bid < MAX_TILES) {
        if (bid >= g_ntiles) return;
        int nb = g_tb[bid]; start = g_ts[bid]; nrows = g_tr[bid];
        w1t = g_wt + OFF_BW1 + (size_t)nb * DD * HH;
        w2t = g_wt + OFF_BW2 + (size_t)nb * HH * HH;
        w3 = bw3 + nb * HH * 3; b1 = bb1 + nb * HH; b2 = bb2 + nb * HH; b3 = bb3 + nb * 3;
        nout = 3; sig = true; obase = out; gather = true;
    } else {
        start = (bid - MAX_TILES) * TM; nrows = TM;
        w1t = g_wt + OFF_OW1; w2t = g_wt + OFF_OW2;
        w3 = ow3; b1 = ob1; b2 = ob2; b3 = ob3;
        nout = 1; sig = false; obase = out + (size_t)3 * BATCH; gather = false;
    }
    if (tid < TM) {
        int i = (tid < nrows) ? tid : (nrows - 1);  // clamp pads; stores guarded
        rid[tid] = gather ? g_idx[start + i] : (start + i);
    }
    __syncthreads();

    unsigned aA = (unsigned)__cvta_generic_to_shared(Asm);
    unsigned aW = (unsigned)__cvta_generic_to_shared(Wsm);
    const unsigned* embU = (const unsigned*)g_emb;

    auto stageA = [&](int kc, int buf) {
#pragma unroll
        for (int u = 0; u < 2; u++) {
            int idx = u * 512 + tid;
            int r = idx >> 3, q = idx & 7;
            cpa16(aA + (unsigned)(buf * 4096 + r * 32 + ((q * 4) ^ ((r & 7) * 4))) * 4u,
                  embU + (size_t)rid[r] * DD + kc * 32 + q * 4);
        }
    };
    auto stageW = [&](const unsigned* wt, int kc, int buf) {
#pragma unroll
        for (int u = 0; u < 4; u++) {
            int idx = u * 512 + tid;
            int k = idx >> 6, q = idx & 63;
            cpa16(aW + (unsigned)(buf * 8192 + k * 256 + ((q * 4) ^ ((k & 3) * 8))) * 4u,
                  wt + (size_t)(kc * 32 + k) * HH + q * 4);
        }
    };

    float acc[2][8][4];
#pragma unroll
    for (int i = 0; i < 2; i++)
#pragma unroll
        for (int j = 0; j < 8; j++)
#pragma unroll
            for (int q = 0; q < 4; q++) acc[i][j][q] = 0.f;

    // ---- layer 1: K = 512, A+W double-buffered ----
    stageA(0, 0); stageW(w1t, 0, 0); CP_COMMIT();
    for (int kc = 0; kc < 16; kc++) {
        if (kc < 15) { stageA(kc + 1, (kc + 1) & 1); stageW(w1t, kc + 1, (kc + 1) & 1);
                       CP_COMMIT(); CP_WAIT1(); }
        else CP_WAIT0();
        __syncthreads();
        int buf = kc & 1;
        mma_chunk<32, true>(Asm + buf * 4096, Wsm + buf * 8192, 0, lane, wm, wn, acc);
        __syncthreads();
    }

    // overlap: issue first L2 weight chunk before h1 writeback
    stageW(w2t, 0, 0); CP_COMMIT();

    // h1 = tf32(relu(acc + b1)) -> Hs; reset acc
#pragma unroll
    for (int mi = 0; mi < 2; mi++) {
        int r = wm * 32 + mi * 16 + (lane >> 2);
#pragma unroll
        for (int ni = 0; ni < 8; ni++) {
            int n = wn * 64 + ni * 8 + 2 * (lane & 3);
            float c0 = b1[n], c1 = b1[n + 1];
            Hs[r * 260 + n]           = __uint_as_float(f2tf(fmaxf(acc[mi][ni][0] + c0, 0.f)));
            Hs[r * 260 + n + 1]       = __uint_as_float(f2tf(fmaxf(acc[mi][ni][1] + c1, 0.f)));
            Hs[(r + 8) * 260 + n]     = __uint_as_float(f2tf(fmaxf(acc[mi][ni][2] + c0, 0.f)));
            Hs[(r + 8) * 260 + n + 1] = __uint_as_float(f2tf(fmaxf(acc[mi][ni][3] + c1, 0.f)));
#pragma unroll
            for (int q = 0; q < 4; q++) acc[mi][ni][q] = 0.f;
        }
    }

    // ---- layer 2: K = 256, A = Hs resident, W double-buffered ----
    for (int kc = 0; kc < 8; kc++) {
        if (kc < 7) { stageW(w2t, kc + 1, (kc + 1) & 1); CP_COMMIT(); CP_WAIT1(); }
        else CP_WAIT0();
        __syncthreads();
        mma_chunk<260, false>((const unsigned*)Hs, Wsm + (kc & 1) * 8192, kc * 32,
                              lane, wm, wn, acc);
        __syncthreads();
    }

    // h2 = relu(acc + b2) -> Hs (fp32 for the scalar epilogue)
#pragma unroll
    for (int mi = 0; mi < 2; mi++) {
        int r = wm * 32 + mi * 16 + (lane >> 2);
#pragma unroll
        for (int ni = 0; ni < 8; ni++) {
            int n = wn * 64 + ni * 8 + 2 * (lane & 3);
            float c0 = b2[n], c1 = b2[n + 1];
            Hs[r * 260 + n]           = fmaxf(acc[mi][ni][0] + c0, 0.f);
            Hs[r * 260 + n + 1]       = fmaxf(acc[mi][ni][1] + c1, 0.f);
            Hs[(r + 8) * 260 + n]     = fmaxf(acc[mi][ni][2] + c0, 0.f);
            Hs[(r + 8) * 260 + n + 1] = fmaxf(acc[mi][ni][3] + c1, 0.f);
        }
    }
    float* W3s = (float*)Asm;  // As buffers free after L1
    for (int idx = tid; idx < HH * nout; idx += 512) W3s[idx] = w3[idx];
    __syncthreads();

    // ---- layer 3 epilogue: one thread per row, lane-rotated k order (conflict-free,
    // deterministic per-thread summation order) ----
    if (tid < nrows) {
        float a3[3] = {0.f, 0.f, 0.f};
#pragma unroll
        for (int o = 0; o < 3; o++)
            if (o < nout) a3[o] = b3[o];
        int rot = (253 * lane) & 255;
#pragma unroll 8
        for (int kk = 0; kk < HH; kk++) {
            int k = (kk + rot) & 255;
            float v = Hs[tid * 260 + k];
#pragma unroll
            for (int o = 0; o < 3; o++)
                if (o < nout) a3[o] = fmaf(v, W3s[k * nout + o], a3[o]);
        }
        size_t orow = (size_t)rid[tid];
#pragma unroll
        for (int o = 0; o < 3; o++)
            if (o < nout) {
                float v = a3[o];
                if (sig) v = 1.f / (1.f + expf(-v));
                obase[orow * nout + o] = v;
            }
    }
}

// ---------------- launch ----------------
extern "C" void kernel_launch(void* const* d_in, const int* in_sizes, int n_in,
                              void* d_out, int out_size) {
    const float* embedding = (const float*)d_in[0];
    const float* speed     = (const float*)d_in[1];
    const int*   command   = (const int*)d_in[2];
    const float* sw1 = (const float*)d_in[3];
    const float* sb1 = (const float*)d_in[4];
    const float* sw2 = (const float*)d_in[5];
    const float* sb2 = (const float*)d_in[6];
    const float* bw1 = (const float*)d_in[7];
    const float* bb1 = (const float*)d_in[8];
    const float* bw2 = (const float*)d_in[9];
    const float* bb2 = (const float*)d_in[10];
    const float* bw3 = (const float*)d_in[11];
    const float* bb3 = (const float*)d_in[12];
    const float* ow1 = (const float*)d_in[13];
    const float* ob1 = (const float*)d_in[14];
    const float* ow2 = (const float*)d_in[15];
    const float* ob2 = (const float*)d_in[16];
    const float* ow3 = (const float*)d_in[17];
    const float* ob3 = (const float*)d_in[18];
    float* out = (float*)d_out;

    const int SMEM_EMB = (32768 + 16384) * 4 + (256 + 256 + 128) * 4;       // 199,168
    const int SMEM_MLP = (33280 + 16384 + 8192) * 4 + 128 * 4;              // 231,936
    cudaFuncSetAttribute((const void*)k_emb,
                         cudaFuncAttributeMaxDynamicSharedMemorySize, SMEM_EMB);
    cudaFuncSetAttribute((const void*)k_mlp_all,
                         cudaFuncAttributeMaxDynamicSharedMemorySize, SMEM_MLP);

    k_cvtw<<<1472, 256>>>(sw2, bw1, bw2, ow1, ow2);
    k_hist<<<BATCH / 256, 256>>>(command);
    k_plan<<<1, 32>>>();
    k_scatter<<<BATCH / 256, 256>>>(command);
    k_emb<<<dim3(BATCH / 128, DD / 256), 512, SMEM_EMB>>>(embedding, speed, sw1, sb1, sb2);
    k_mlp_all<<<MAX_TILES + BATCH / TM, 512, SMEM_MLP>>>(bb1, bb2, bw3, bb3,
                                                         ob1, ob2, ow3, ob3, out);
}

// round 7
// speedup vs baseline: 3.2342x; 1.0103x over previous
#include <cuda_runtime.h>
#include <math.h>

#define BATCH 65536
#define DD 512
#define HH 256
#define NBR 6
#define TM 128
#define MAX_TILES (BATCH / TM + NBR)   // 518

// tf32 weight scratch offsets (in unsigned elements)
#define OFF_SW2 0
#define OFF_BW1 131072
#define OFF_BW2 917504
#define OFF_OW1 1310720
#define OFF_OW2 1441792
#define WT_TOTAL 1507328

// ---------------- scratch (static __device__, no allocs) ----------------
__device__ float g_emb[(size_t)BATCH * DD];   // holds tf32 BIT PATTERNS of emb
__device__ unsigned g_wt[WT_TOTAL];           // pre-rounded tf32 weights
__device__ int g_idx[BATCH];
__device__ int g_counts[NBR];
__device__ int g_cursor[NBR];
__device__ int g_tb[MAX_TILES], g_ts[MAX_TILES], g_tr[MAX_TILES];
__device__ int g_ntiles;

// ---------------- helpers ----------------
__device__ __forceinline__ unsigned f2tf(float f) {
    unsigned r;
    asm("cvt.rn.tf32.f32 %0, %1;" : "=r"(r) : "f"(f));
    return r;
}

__device__ __forceinline__ void mma_tf32(float* d, const unsigned* a, const unsigned* b) {
    asm volatile(
        "mma.sync.aligned.m16n8k8.row.col.f32.tf32.tf32.f32 "
        "{%0,%1,%2,%3},{%4,%5,%6,%7},{%8,%9},{%0,%1,%2,%3};"
        : "+f"(d[0]), "+f"(d[1]), "+f"(d[2]), "+f"(d[3])
        : "r"(a[0]), "r"(a[1]), "r"(a[2]), "r"(a[3]), "r"(b[0]), "r"(b[1]));
}

__device__ __forceinline__ void cpa16(unsigned dst, const void* src) {
    asm volatile("cp.async.cg.shared.global [%0], [%1], 16;" :: "r"(dst), "l"(src) : "memory");
}
#define CP_COMMIT() asm volatile("cp.async.commit_group;" ::: "memory")
#define CP_WAIT0()  asm volatile("cp.async.wait_group 0;" ::: "memory")
#define CP_WAIT1()  asm volatile("cp.async.wait_group 1;" ::: "memory")

// One K=32 chunk of mma for a 128x256 block (16 warps, warp tile 32x64).
// A: stride LDAe; SWZ -> columns XOR-swizzled by 4*(r&7). W: stride 256, swizzled by 8*(k&3).
template <int LDAe, bool SWZ>
__device__ __forceinline__ void mma_chunk(const unsigned* __restrict__ A,
                                          const unsigned* __restrict__ W,
                                          int cbase, int lane, int wm, int wn,
                                          float acc[2][8][4]) {
    int swa = (lane >> 2) * 4;
    int swb = (lane & 3) * 8;
#pragma unroll
    for (int ks = 0; ks < 4; ks++) {
        int kk = ks * 8;
        unsigned a[2][4], b[8][2];
#pragma unroll
        for (int mi = 0; mi < 2; mi++) {
            int r = wm * 32 + mi * 16 + (lane >> 2);
            int c = cbase + kk + (lane & 3);
            int c1 = SWZ ? (c ^ swa) : c;
            int c2 = SWZ ? ((c + 4) ^ swa) : (c + 4);
            a[mi][0] = A[r * LDAe + c1];
            a[mi][1] = A[(r + 8) * LDAe + c1];
            a[mi][2] = A[r * LDAe + c2];
            a[mi][3] = A[(r + 8) * LDAe + c2];
        }
#pragma unroll
        for (int ni = 0; ni < 8; ni++) {
            int n = (wn * 64 + ni * 8 + (lane >> 2)) ^ swb;
            int k = kk + (lane & 3);
            b[ni][0] = W[k * 256 + n];
            b[ni][1] = W[(k + 4) * 256 + n];
        }
#pragma unroll
        for (int mi = 0; mi < 2; mi++)
#pragma unroll
            for (int ni = 0; ni < 8; ni++) mma_tf32(acc[mi][ni], a[mi], b[ni]);
    }
}

// ---------------- setup: weight pre-conversion + counts zero ----------------
__global__ void k_cvtw(const float* __restrict__ sw2, const float* __restrict__ bw1,
                       const float* __restrict__ bw2, const float* __restrict__ ow1,
                       const float* __restrict__ ow2) {
    int i = blockIdx.x * 256 + threadIdx.x;  // float4 index, total 376832
    const float* src;
    int base;
    if (i < 32768)       { src = sw2; base = 0; }
    else if (i < 229376) { src = bw1; base = 32768; }
    else if (i < 327680) { src = bw2; base = 229376; }
    else if (i < 360448) { src = ow1; base = 327680; }
    else                 { src = ow2; base = 360448; }
    float4 v = ((const float4*)src)[i - base];
    uint4 o = {f2tf(v.x), f2tf(v.y), f2tf(v.z), f2tf(v.w)};
    ((uint4*)g_wt)[i] = o;
    if (blockIdx.x == 0 && threadIdx.x < NBR) g_counts[threadIdx.x] = 0;
}

// ---------------- bucketing ----------------
__global__ void k_hist(const int* __restrict__ cmd) {
    __shared__ int c[NBR];
    int t = threadIdx.x;
    if (t < NBR) c[t] = 0;
    __syncthreads();
    atomicAdd(&c[cmd[blockIdx.x * 256 + t] - 1], 1);
    __syncthreads();
    if (t < NBR) atomicAdd(&g_counts[t], c[t]);
}

__global__ void k_plan() {
    int l = threadIdx.x;
    int c[NBR], base[NBR], tp[NBR];
    int b = 0, t = 0;
#pragma unroll
    for (int n = 0; n < NBR; n++) {
        c[n] = g_counts[n]; base[n] = b; tp[n] = t;
        b += c[n]; t += (c[n] + TM - 1) / TM;
    }
    for (int tile = l; tile < t; tile += 32) {
        int n = 0;
        while (n < NBR - 1 && tile >= tp[n + 1]) n++;
        int loc = tile - tp[n];
        g_tb[tile] = n;
        g_ts[tile] = base[n] + loc * TM;
        int rem = c[n] - loc * TM;
        g_tr[tile] = rem < TM ? rem : TM;
    }
    if (l == 0) g_ntiles = t;
    if (l < NBR) g_cursor[l] = base[l];
}

__global__ void k_scatter(const int* __restrict__ cmd) {
    __shared__ int lc[NBR], lb[NBR];
    int t = threadIdx.x;
    if (t < NBR) lc[t] = 0;
    __syncthreads();
    int r = blockIdx.x * 256 + t;
    int b = cmd[r] - 1;
    int rank = atomicAdd(&lc[b], 1);
    __syncthreads();
    if (t < NBR) lb[t] = atomicAdd(&g_cursor[t], lc[t]);
    __syncthreads();
    g_idx[lb[b] + rank] = r;  // per-row math downstream independent of permutation
}

// ---------------- emb = tf32(embedding + relu(speed*sw1+sb1) @ sw2 + sb2) ----------------
// block 128 rows x 256 cols, 512 threads, K=HH chunked by 32, W double-buffered cp.async
__global__ __launch_bounds__(512, 1) void k_emb(
    const float* __restrict__ embedding, const float* __restrict__ speed,
    const float* __restrict__ sw1, const float* __restrict__ sb1,
    const float* __restrict__ sb2) {
    extern __shared__ float smf[];
    unsigned* Asf = (unsigned*)smf;        // 128*256 swizzled, full K
    unsigned* Wsm = Asf + 32768;           // 2 x 32*256 swizzled
    float* sw1s = (float*)(Wsm + 16384);   // 256
    float* sb1s = sw1s + 256;              // 256
    float* Sp = sb1s + 256;                // 128

    int tid = threadIdx.x, lane = tid & 31, w = tid >> 5;
    int wm = w & 3, wn = w >> 2;
    int row0 = blockIdx.x * 128, col0 = blockIdx.y * 256;

    if (tid < 128) Sp[tid] = speed[row0 + tid];
    if (tid < 256) { sw1s[tid] = sw1[tid]; sb1s[tid] = sb1[tid]; }
    __syncthreads();

    for (int u = 0; u < 64; u++) {
        int idx = u * 512 + tid;
        int r = idx >> 8, c = idx & 255;
        float v = fmaxf(fmaf(Sp[r], sw1s[c], sb1s[c]), 0.f);
        Asf[r * 256 + (c ^ ((r & 7) * 4))] = f2tf(v);
    }

    unsigned aW = (unsigned)__cvta_generic_to_shared(Wsm);
    const unsigned* wt = g_wt + OFF_SW2;

    float acc[2][8][4];
#pragma unroll
    for (int i = 0; i < 2; i++)
#pragma unroll
        for (int j = 0; j < 8; j++)
#pragma unroll
            for (int q = 0; q < 4; q++) acc[i][j][q] = 0.f;

    // stage W chunk kc into buf
    auto stage = [&](int kc, int buf) {
#pragma unroll
        for (int u = 0; u < 4; u++) {
            int idx = u * 512 + tid;
            int k = idx >> 6, q = idx & 63;
            cpa16(aW + (unsigned)(buf * 8192 + k * 256 + ((q * 4) ^ ((k & 3) * 8))) * 4u,
                  wt + (size_t)(kc * 32 + k) * DD + col0 + q * 4);
        }
    };

    stage(0, 0); CP_COMMIT();
    for (int kc = 0; kc < 8; kc++) {
        if (kc < 7) { stage(kc + 1, (kc + 1) & 1); CP_COMMIT(); CP_WAIT1(); }
        else CP_WAIT0();
        __syncthreads();
        mma_chunk<256, true>(Asf, Wsm + (kc & 1) * 8192, kc * 32, lane, wm, wn, acc);
        __syncthreads();
    }

    unsigned* gE = (unsigned*)g_emb;
#pragma unroll
    for (int mi = 0; mi < 2; mi++) {
        int r = row0 + wm * 32 + mi * 16 + (lane >> 2);
#pragma unroll
        for (int ni = 0; ni < 8; ni++) {
            int n = col0 + wn * 64 + ni * 8 + 2 * (lane & 3);
            float s0 = sb2[n], s1 = sb2[n + 1];
            {
                size_t ix = (size_t)r * DD + n;
                float2 e = *(const float2*)&embedding[ix];
                uint2 o = {f2tf(acc[mi][ni][0] + e.x + s0), f2tf(acc[mi][ni][1] + e.y + s1)};
                *(uint2*)&gE[ix] = o;
            }
            {
                size_t ix = (size_t)(r + 8) * DD + n;
                float2 e = *(const float2*)&embedding[ix];
                uint2 o = {f2tf(acc[mi][ni][2] + e.x + s0), f2tf(acc[mi][ni][3] + e.y + s1)};
                *(uint2*)&gE[ix] = o;
            }
        }
    }
}

// ---------------- fused 3-layer MLP, both heads in one launch ----------------
// bid < MAX_TILES: branch-pure gathered tile (NOUT=3, sigmoid); else speed head tile.
__global__ __launch_bounds__(512, 1) void k_mlp_all(
    const float* __restrict__ bb1, const float* __restrict__ bb2,
    const float* __restrict__ bw3, const float* __restrict__ bb3,
    const float* __restrict__ ob1, const float* __restrict__ ob2,
    const float* __restrict__ ow3, const float* __restrict__ ob3,
    float* __restrict__ out) {
    extern __shared__ float smf[];
    float* Hs = smf;                              // 128*260 (padded, conflict-free)
    unsigned* Wsm = (unsigned*)(smf + 33280);     // 2 x 32*256 swizzled
    unsigned* Asm = Wsm + 16384;                  // 2 x 128*32 swizzled
    int* rid = (int*)(Asm + 8192);                // 128

    int tid = threadIdx.x, lane = tid & 31, w = tid >> 5;
    int wm = w & 3, wn = w >> 2;
    int bid = blockIdx.x;

    const unsigned *w1t, *w2t;
    const float *w3, *b1, *b2, *b3;
    float* obase;
    int nout, start, nrows;
    bool sig, gather;
    if (bid < MAX_TILES) {
        if (bid >= g_ntiles) return;
        int nb = g_tb[bid]; start = g_ts[bid]; nrows = g_tr[bid];
        w1t = g_wt + OFF_BW1 + (size_t)nb * DD * HH;
        w2t = g_wt + OFF_BW2 + (size_t)nb * HH * HH;
        w3 = bw3 + nb * HH * 3; b1 = bb1 + nb * HH; b2 = bb2 + nb * HH; b3 = bb3 + nb * 3;
        nout = 3; sig = true; obase = out; gather = true;
    } else {
        start = (bid - MAX_TILES) * TM; nrows = TM;
        w1t = g_wt + OFF_OW1; w2t = g_wt + OFF_OW2;
        w3 = ow3; b1 = ob1; b2 = ob2; b3 = ob3;
        nout = 1; sig = false; obase = out + (size_t)3 * BATCH; gather = false;
    }
    if (tid < TM) {
        int i = (tid < nrows) ? tid : (nrows - 1);  // clamp pads; stores guarded
        rid[tid] = gather ? g_idx[start + i] : (start + i);
    }
    __syncthreads();

    unsigned aA = (unsigned)__cvta_generic_to_shared(Asm);
    unsigned aW = (unsigned)__cvta_generic_to_shared(Wsm);
    const unsigned* embU = (const unsigned*)g_emb;

    auto stageA = [&](int kc, int buf) {
#pragma unroll
        for (int u = 0; u < 2; u++) {
            int idx = u * 512 + tid;
            int r = idx >> 3, q = idx & 7;
            cpa16(aA + (unsigned)(buf * 4096 + r * 32 + ((q * 4) ^ ((r & 7) * 4))) * 4u,
                  embU + (size_t)rid[r] * DD + kc * 32 + q * 4);
        }
    };
    auto stageW = [&](const unsigned* wt, int kc, int buf) {
#pragma unroll
        for (int u = 0; u < 4; u++) {
            int idx = u * 512 + tid;
            int k = idx >> 6, q = idx & 63;
            cpa16(aW + (unsigned)(buf * 8192 + k * 256 + ((q * 4) ^ ((k & 3) * 8))) * 4u,
                  wt + (size_t)(kc * 32 + k) * HH + q * 4);
        }
    };

    float acc[2][8][4];
#pragma unroll
    for (int i = 0; i < 2; i++)
#pragma unroll
        for (int j = 0; j < 8; j++)
#pragma unroll
            for (int q = 0; q < 4; q++) acc[i][j][q] = 0.f;

    // ---- layer 1: K = 512, A+W double-buffered ----
    stageA(0, 0); stageW(w1t, 0, 0); CP_COMMIT();
    for (int kc = 0; kc < 16; kc++) {
        if (kc < 15) { stageA(kc + 1, (kc + 1) & 1); stageW(w1t, kc + 1, (kc + 1) & 1);
                       CP_COMMIT(); CP_WAIT1(); }
        else CP_WAIT0();
        __syncthreads();
        int buf = kc & 1;
        mma_chunk<32, true>(Asm + buf * 4096, Wsm + buf * 8192, 0, lane, wm, wn, acc);
        __syncthreads();
    }

    // overlap: issue first L2 weight chunk before h1 writeback
    stageW(w2t, 0, 0); CP_COMMIT();

    // h1 = tf32(relu(acc + b1)) -> Hs; reset acc
#pragma unroll
    for (int mi = 0; mi < 2; mi++) {
        int r = wm * 32 + mi * 16 + (lane >> 2);
#pragma unroll
        for (int ni = 0; ni < 8; ni++) {
            int n = wn * 64 + ni * 8 + 2 * (lane & 3);
            float c0 = b1[n], c1 = b1[n + 1];
            Hs[r * 260 + n]           = __uint_as_float(f2tf(fmaxf(acc[mi][ni][0] + c0, 0.f)));
            Hs[r * 260 + n + 1]       = __uint_as_float(f2tf(fmaxf(acc[mi][ni][1] + c1, 0.f)));
            Hs[(r + 8) * 260 + n]     = __uint_as_float(f2tf(fmaxf(acc[mi][ni][2] + c0, 0.f)));
            Hs[(r + 8) * 260 + n + 1] = __uint_as_float(f2tf(fmaxf(acc[mi][ni][3] + c1, 0.f)));
#pragma unroll
            for (int q = 0; q < 4; q++) acc[mi][ni][q] = 0.f;
        }
    }

    // ---- layer 2: K = 256, A = Hs resident, W double-buffered ----
    for (int kc = 0; kc < 8; kc++) {
        if (kc < 7) { stageW(w2t, kc + 1, (kc + 1) & 1); CP_COMMIT(); CP_WAIT1(); }
        else CP_WAIT0();
        __syncthreads();
        mma_chunk<260, false>((const unsigned*)Hs, Wsm + (kc & 1) * 8192, kc * 32,
                              lane, wm, wn, acc);
        __syncthreads();
    }

    // h2 = relu(acc + b2) -> Hs (fp32 for the scalar epilogue)
#pragma unroll
    for (int mi = 0; mi < 2; mi++) {
        int r = wm * 32 + mi * 16 + (lane >> 2);
#pragma unroll
        for (int ni = 0; ni < 8; ni++) {
            int n = wn * 64 + ni * 8 + 2 * (lane & 3);
            float c0 = b2[n], c1 = b2[n + 1];
            Hs[r * 260 + n]           = fmaxf(acc[mi][ni][0] + c0, 0.f);
            Hs[r * 260 + n + 1]       = fmaxf(acc[mi][ni][1] + c1, 0.f);
            Hs[(r + 8) * 260 + n]     = fmaxf(acc[mi][ni][2] + c0, 0.f);
            Hs[(r + 8) * 260 + n + 1] = fmaxf(acc[mi][ni][3] + c1, 0.f);
        }
    }
    float* W3s = (float*)Asm;  // As buffers free after L1
    for (int idx = tid; idx < HH * nout; idx += 512) W3s[idx] = w3[idx];
    __syncthreads();

    // ---- layer 3 epilogue: one thread per row, lane-rotated k order (conflict-free,
    // deterministic per-thread summation order) ----
    if (tid < nrows) {
        float a3[3] = {0.f, 0.f, 0.f};
#pragma unroll
        for (int o = 0; o < 3; o++)
            if (o < nout) a3[o] = b3[o];
        int rot = (253 * lane) & 255;
#pragma unroll 8
        for (int kk = 0; kk < HH; kk++) {
            int k = (kk + rot) & 255;
            float v = Hs[tid * 260 + k];
#pragma unroll
            for (int o = 0; o < 3; o++)
                if (o < nout) a3[o] = fmaf(v, W3s[k * nout + o], a3[o]);
        }
        size_t orow = (size_t)rid[tid];
#pragma unroll
        for (int o = 0; o < 3; o++)
            if (o < nout) {
                float v = a3[o];
                if (sig) v = 1.f / (1.f + expf(-v));
                obase[orow * nout + o] = v;
            }
    }
}

// ---------------- launch ----------------
extern "C" void kernel_launch(void* const* d_in, const int* in_sizes, int n_in,
                              void* d_out, int out_size) {
    const float* embedding = (const float*)d_in[0];
    const float* speed     = (const float*)d_in[1];
    const int*   command   = (const int*)d_in[2];
    const float* sw1 = (const float*)d_in[3];
    const float* sb1 = (const float*)d_in[4];
    const float* sw2 = (const float*)d_in[5];
    const float* sb2 = (const float*)d_in[6];
    const float* bw1 = (const float*)d_in[7];
    const float* bb1 = (const float*)d_in[8];
    const float* bw2 = (const float*)d_in[9];
    const float* bb2 = (const float*)d_in[10];
    const float* bw3 = (const float*)d_in[11];
    const float* bb3 = (const float*)d_in[12];
    const float* ow1 = (const float*)d_in[13];
    const float* ob1 = (const float*)d_in[14];
    const float* ow2 = (const float*)d_in[15];
    const float* ob2 = (const float*)d_in[16];
    const float* ow3 = (const float*)d_in[17];
    const float* ob3 = (const float*)d_in[18];
    float* out = (float*)d_out;

    const int SMEM_EMB = (32768 + 16384) * 4 + (256 + 256 + 128) * 4;       // 199,168
    const int SMEM_MLP = (33280 + 16384 + 8192) * 4 + 128 * 4;              // 231,936
    cudaFuncSetAttribute((const void*)k_emb,
                         cudaFuncAttributeMaxDynamicSharedMemorySize, SMEM_EMB);
    cudaFuncSetAttribute((const void*)k_mlp_all,
                         cudaFuncAttributeMaxDynamicSharedMemorySize, SMEM_MLP);

    k_cvtw<<<1472, 256>>>(sw2, bw1, bw2, ow1, ow2);
    k_hist<<<BATCH / 256, 256>>>(command);
    k_plan<<<1, 32>>>();
    k_scatter<<<BATCH / 256, 256>>>(command);
    k_emb<<<dim3(BATCH / 128, DD / 256), 512, SMEM_EMB>>>(embedding, speed, sw1, sb1, sb2);
    k_mlp_all<<<MAX_TILES + BATCH / TM, 512, SMEM_MLP>>>(bb1, bb2, bw3, bb3,
                                                         ob1, ob2, ow3, ob3, out);
}

// round 12
// speedup vs baseline: 5.3273x; 1.6472x over previous
#include <cuda_runtime.h>
#include <cuda_fp16.h>
#include <math.h>
#include <stdint.h>

#define BATCH 65536
#define DD 512
#define HH 256
#define NBR 6
#define TM 128
#define MAX_TILES (BATCH / TM + NBR)   // 518

// packed-half2 weight scratch, word offsets. All MLP/emb weights transposed to
// per-chunk tiles [kc][n][16 words] (16 words = 32 k-halves).
#define OFF_SW2T 0         // 8 kc x 512 n x 16
#define OFF_BW1  65536     // 6 x (16 kc x 256 x 16)
#define OFF_BW2  458752    // 6 x (8 kc x 256 x 16)
#define OFF_OW1  655360    // 16 kc x 256 x 16
#define OFF_OW2  720896    // 8 kc x 256 x 16
#define WT_TOTAL 753664

// ---- k_mlp smem word map ----
#define HS 0          // 128 x 132 (h1 half2, stride-132 pad)
#define WB 16896      // 2 x 4096  (W chunk bufs [256][16], XOR swizzle)
#define AB 25088      // 2 x 2048  (A chunk bufs [128][16], XOR swizzle)
#define B1S 29184     // 256
#define B2S 29440     // 256
#define W3S 29696     // 768
#define RED 30464     // 1536
#define RIDW 32000    // 128
#define MLP_WORDS 32128   // 128,512 B

// ---- k_emb smem word map ----
#define EA 0          // 128 x 132 (A half2, resident full K)
#define EW 16896      // 2 x 4096
#define ESP 25088     // 128
#define ESW1 25216    // 256
#define ESB1 25472    // 256
#define EMB_WORDS 25728   // 102,912 B

__device__ unsigned g_emb[(size_t)BATCH * 256];  // emb as packed half2 (64 MB)
__device__ unsigned g_wt[WT_TOTAL];
__device__ int g_idx[BATCH];
__device__ int g_counts[NBR];
__device__ int g_cursor[NBR];
__device__ int g_tb[MAX_TILES], g_ts[MAX_TILES], g_tr[MAX_TILES];
__device__ int g_ntiles;

// ---------------- helpers ----------------
__device__ __forceinline__ unsigned f2h2(float lo, float hi) {
    __half2 h = __floats2half2_rn(lo, hi);
    return *(unsigned*)&h;
}
__device__ __forceinline__ void cpa16(unsigned dst, const void* src) {
    asm volatile("cp.async.cg.shared.global [%0], [%1], 16;" :: "r"(dst), "l"(src) : "memory");
}
#define CP_COMMIT() asm volatile("cp.async.commit_group;" ::: "memory")
#define CP_WAIT0()  asm volatile("cp.async.wait_group 0;" ::: "memory")
#define CP_WAIT1()  asm volatile("cp.async.wait_group 1;" ::: "memory")

// m16n8k16 fp16 inputs, fp32 accumulate
__device__ __forceinline__ void mma_f16(float* d, const unsigned* a, const unsigned* b) {
    asm volatile(
        "mma.sync.aligned.m16n8k16.row.col.f32.f16.f16.f32 "
        "{%0,%1,%2,%3},{%4,%5,%6,%7},{%8,%9},{%0,%1,%2,%3};"
        : "+f"(d[0]), "+f"(d[1]), "+f"(d[2]), "+f"(d[3])
        : "r"(a[0]), "r"(a[1]), "r"(a[2]), "r"(a[3]), "r"(b[0]), "r"(b[1]));
}

// One K=32-half chunk for a 128x256 block tile (16 warps, warp tile 32x64).
// A: XORA -> [128][16] XOR-swizzled chunk buf (stride 16); else resident stride-132, col base cbase.
// W: [256][16] XOR-swizzled buf.
template <bool XORA>
__device__ __forceinline__ void mma_chunk16(const unsigned* __restrict__ A, int astride,
                                            const unsigned* __restrict__ W,
                                            int cbase, int lane, int wm, int wn,
                                            float acc[2][8][4]) {
#pragma unroll
    for (int ks = 0; ks < 2; ks++) {
        unsigned a[2][4], b[8][2];
#pragma unroll
        for (int mi = 0; mi < 2; mi++) {
            int r = wm * 32 + mi * 16 + (lane >> 2);
            int c = cbase + ks * 8 + (lane & 3);
            int xr = XORA ? 4 * ((r >> 1) & 3) : 0;
            a[mi][0] = A[r * astride + (XORA ? (c ^ xr) : c)];
            a[mi][1] = A[(r + 8) * astride + (XORA ? (c ^ (4 * (((r + 8) >> 1) & 3))) : c)];
            a[mi][2] = A[r * astride + (XORA ? ((c + 4) ^ xr) : (c + 4))];
            a[mi][3] = A[(r + 8) * astride + (XORA ? ((c + 4) ^ (4 * (((r + 8) >> 1) & 3))) : (c + 4))];
        }
#pragma unroll
        for (int ni = 0; ni < 8; ni++) {
            int n = wn * 64 + ni * 8 + (lane >> 2);
            int xn = 4 * ((n >> 1) & 3);
            int wsel = ks * 8 + (lane & 3);
            b[ni][0] = W[n * 16 + (wsel ^ xn)];
            b[ni][1] = W[n * 16 + ((wsel + 4) ^ xn)];
        }
#pragma unroll
        for (int mi = 0; mi < 2; mi++)
#pragma unroll
            for (int ni = 0; ni < 8; ni++) mma_f16(acc[mi][ni], a[mi], b[ni]);
    }
}

// ---------------- setup: convert+transpose weights to packed half2, zero counts ----------------
__global__ void k_cvtw(const float* __restrict__ sw2, const float* __restrict__ bw1,
                       const float* __restrict__ bw2, const float* __restrict__ ow1,
                       const float* __restrict__ ow2) {
    int i = blockIdx.x * 256 + threadIdx.x;  // uint4 idx over 188416
    int wi = i * 4;
    const float* src; int N, kc, n, w;
    if (wi < 65536) {
        src = sw2; N = 512;
        kc = wi >> 13; int rem = wi & 8191; n = rem >> 4; w = rem & 15;
    } else if (wi < 458752) {
        int r = wi - 65536; int b = r >> 16; int rem = r & 65535;
        src = bw1 + (size_t)b * DD * HH; N = 256;
        kc = rem >> 12; n = (rem >> 4) & 255; w = rem & 15;
    } else if (wi < 655360) {
        int r = wi - 458752; int b = r >> 15; int rem = r & 32767;
        src = bw2 + (size_t)b * HH * HH; N = 256;
        kc = rem >> 12; n = (rem >> 4) & 255; w = rem & 15;
    } else if (wi < 720896) {
        int r = wi - 655360; src = ow1; N = 256;
        kc = r >> 12; n = (r >> 4) & 255; w = r & 15;
    } else {
        int r = wi - 720896; src = ow2; N = 256;
        kc = r >> 12; n = (r >> 4) & 255; w = r & 15;
    }
    uint4 o;
    int k0 = kc * 32 + 2 * w;
    o.x = f2h2(src[(size_t)(k0 + 0) * N + n], src[(size_t)(k0 + 1) * N + n]);
    o.y = f2h2(src[(size_t)(k0 + 2) * N + n], src[(size_t)(k0 + 3) * N + n]);
    o.z = f2h2(src[(size_t)(k0 + 4) * N + n], src[(size_t)(k0 + 5) * N + n]);
    o.w = f2h2(src[(size_t)(k0 + 6) * N + n], src[(size_t)(k0 + 7) * N + n]);
    ((uint4*)g_wt)[i] = o;
    if (blockIdx.x == 0 && threadIdx.x < NBR) g_counts[threadIdx.x] = 0;
}

// ---------------- bucketing (proven) ----------------
__global__ void k_hist(const int* __restrict__ cmd) {
    __shared__ int c[NBR];
    int t = threadIdx.x;
    if (t < NBR) c[t] = 0;
    __syncthreads();
    atomicAdd(&c[cmd[blockIdx.x * 256 + t] - 1], 1);
    __syncthreads();
    if (t < NBR) atomicAdd(&g_counts[t], c[t]);
}

__global__ void k_plan() {
    int l = threadIdx.x;
    int c[NBR], base[NBR], tp[NBR];
    int b = 0, t = 0;
#pragma unroll
    for (int n = 0; n < NBR; n++) {
        c[n] = g_counts[n]; base[n] = b; tp[n] = t;
        b += c[n]; t += (c[n] + TM - 1) / TM;
    }
    for (int tile = l; tile < t; tile += 32) {
        int n = 0;
        while (n < NBR - 1 && tile >= tp[n + 1]) n++;
        int loc = tile - tp[n];
        g_tb[tile] = n;
        g_ts[tile] = base[n] + loc * TM;
        int rem = c[n] - loc * TM;
        g_tr[tile] = rem < TM ? rem : TM;
    }
    if (l == 0) g_ntiles = t;
    if (l < NBR) g_cursor[l] = base[l];
}

__global__ void k_scatter(const int* __restrict__ cmd) {
    __shared__ int lc[NBR], lb[NBR];
    int t = threadIdx.x;
    if (t < NBR) lc[t] = 0;
    __syncthreads();
    int r = blockIdx.x * 256 + t;
    int b = cmd[r] - 1;
    int rank = atomicAdd(&lc[b], 1);
    __syncthreads();
    if (t < NBR) lb[t] = atomicAdd(&g_cursor[t], lc[t]);
    __syncthreads();
    g_idx[lb[b] + rank] = r;  // downstream math independent of permutation
}

// ---------------- emb = fp16(embedding + relu(speed*sw1+sb1) @ sw2 + sb2) ----------------
__global__ __launch_bounds__(512, 1) void k_emb(
    const float* __restrict__ embedding, const float* __restrict__ speed,
    const float* __restrict__ sw1, const float* __restrict__ sb1,
    const float* __restrict__ sb2) {
    extern __shared__ unsigned smu[];
    float* smf = (float*)smu;
    int tid = threadIdx.x, lane = tid & 31, w = tid >> 5;
    int wm = w & 3, wn = w >> 2;
    int row0 = blockIdx.x * 128, col0 = blockIdx.y * 256;
    unsigned sb = (unsigned)__cvta_generic_to_shared(smu);

    if (tid < 128) smf[ESP + tid] = speed[row0 + tid];
    if (tid < 256) { smf[ESW1 + tid] = sw1[tid]; smf[ESB1 + tid] = sb1[tid]; }
    __syncthreads();

    auto stageW = [&](int kc, int buf) {
#pragma unroll
        for (int u = 0; u < 2; u++) {
            int idx = u * 512 + tid;          // 1024 uint4
            int n = idx >> 2, q = idx & 3;
            cpa16(sb + (unsigned)(EW + buf * 4096 + n * 16 + ((q * 4) ^ (4 * ((n >> 1) & 3)))) * 4u,
                  g_wt + OFF_SW2T + (size_t)kc * 8192 + (size_t)(col0 + n) * 16 + q * 4);
        }
    };

    stageW(0, 0); CP_COMMIT();
    // build A = relu(speed*sw1+sb1) as half2, stride-132 rows
    for (int u = 0; u < 32; u++) {
        int idx = u * 512 + tid;
        int r = idx >> 7, ww = idx & 127;
        float v0 = fmaxf(fmaf(smf[ESP + r], smf[ESW1 + 2 * ww], smf[ESB1 + 2 * ww]), 0.f);
        float v1 = fmaxf(fmaf(smf[ESP + r], smf[ESW1 + 2 * ww + 1], smf[ESB1 + 2 * ww + 1]), 0.f);
        smu[EA + r * 132 + ww] = f2h2(v0, v1);
    }

    float acc[2][8][4];
#pragma unroll
    for (int i = 0; i < 2; i++)
#pragma unroll
        for (int j = 0; j < 8; j++)
#pragma unroll
            for (int q = 0; q < 4; q++) acc[i][j][q] = 0.f;

    for (int kc = 0; kc < 8; kc++) {
        if (kc < 7) { stageW(kc + 1, (kc + 1) & 1); CP_COMMIT(); CP_WAIT1(); }
        else CP_WAIT0();
        __syncthreads();
        mma_chunk16<false>(smu + EA, 132, smu + EW + (kc & 1) * 4096, kc * 16,
                           lane, wm, wn, acc);
        __syncthreads();
    }

#pragma unroll
    for (int mi = 0; mi < 2; mi++) {
        int r = row0 + wm * 32 + mi * 16 + (lane >> 2);
#pragma unroll
        for (int ni = 0; ni < 8; ni++) {
            int n = col0 + wn * 64 + ni * 8 + 2 * (lane & 3);
            float s0 = sb2[n], s1 = sb2[n + 1];
            {
                float2 e = *(const float2*)&embedding[(size_t)r * DD + n];
                g_emb[(size_t)r * 256 + (n >> 1)] =
                    f2h2(acc[mi][ni][0] + e.x + s0, acc[mi][ni][1] + e.y + s1);
            }
            {
                float2 e = *(const float2*)&embedding[(size_t)(r + 8) * DD + n];
                g_emb[(size_t)(r + 8) * 256 + (n >> 1)] =
                    f2h2(acc[mi][ni][2] + e.x + s0, acc[mi][ni][3] + e.y + s1);
            }
        }
    }
}

// ---------------- fused 3-layer MLP (fp16 mma, both heads, one launch) ----------------
__global__ __launch_bounds__(512, 1) void k_mlp(
    const float* __restrict__ bb1, const float* __restrict__ bb2,
    const float* __restrict__ bw3, const float* __restrict__ bb3,
    const float* __restrict__ ob1, const float* __restrict__ ob2,
    const float* __restrict__ ow3, const float* __restrict__ ob3,
    float* __restrict__ out) {
    extern __shared__ unsigned smu[];
    float* smf = (float*)smu;
    int tid = threadIdx.x, lane = tid & 31, w = tid >> 5;
    int wm = w & 3, wn = w >> 2;
    int bid = blockIdx.x;
    unsigned sb = (unsigned)__cvta_generic_to_shared(smu);

    const unsigned *w1t, *w2t;
    const float *w3, *b1, *b2, *b3;
    float* obase;
    int nout, start, nrows;
    bool sig, gather;
    if (bid < MAX_TILES) {
        if (bid >= g_ntiles) return;
        int nb = g_tb[bid]; start = g_ts[bid]; nrows = g_tr[bid];
        w1t = g_wt + OFF_BW1 + (size_t)nb * 65536;
        w2t = g_wt + OFF_BW2 + (size_t)nb * 32768;
        w3 = bw3 + nb * HH * 3; b1 = bb1 + nb * HH; b2 = bb2 + nb * HH; b3 = bb3 + nb * 3;
        nout = 3; sig = true; obase = out; gather = true;
    } else {
        start = (bid - MAX_TILES) * TM; nrows = TM;
        w1t = g_wt + OFF_OW1; w2t = g_wt + OFF_OW2;
        w3 = ow3; b1 = ob1; b2 = ob2; b3 = ob3;
        nout = 1; sig = false; obase = out + (size_t)3 * BATCH; gather = false;
    }
    if (tid < TM) {
        int i = (tid < nrows) ? tid : (nrows - 1);  // clamp pads; stores guarded
        ((int*)(smu + RIDW))[tid] = gather ? g_idx[start + i] : (start + i);
    }
    if (tid < 256) { smf[B1S + tid] = b1[tid]; smf[B2S + tid] = b2[tid]; }
    for (int idx = tid; idx < HH * nout; idx += 512) smf[W3S + idx] = w3[idx];
    __syncthreads();
    const int* rid = (const int*)(smu + RIDW);

    auto stageA = [&](int kc, int buf) {
        int r = tid >> 2, q = tid & 3;  // 512 uint4
        cpa16(sb + (unsigned)(AB + buf * 2048 + r * 16 + ((q * 4) ^ (4 * ((r >> 1) & 3)))) * 4u,
              g_emb + (size_t)rid[r] * 256 + kc * 16 + q * 4);
    };
    auto stageW = [&](const unsigned* wt, int kc, int buf) {
#pragma unroll
        for (int u = 0; u < 2; u++) {
            int idx = u * 512 + tid;
            int n = idx >> 2, q = idx & 3;
            cpa16(sb + (unsigned)(WB + buf * 4096 + n * 16 + ((q * 4) ^ (4 * ((n >> 1) & 3)))) * 4u,
                  wt + (size_t)kc * 4096 + n * 16 + q * 4);
        }
    };

    float acc[2][8][4];
#pragma unroll
    for (int i = 0; i < 2; i++)
#pragma unroll
        for (int j = 0; j < 8; j++)
#pragma unroll
            for (int q = 0; q < 4; q++) acc[i][j][q] = 0.f;

    // ---- layer 1: K = 512 halves, 16 chunks, A+W double-buffered ----
    stageA(0, 0); stageW(w1t, 0, 0); CP_COMMIT();
    for (int kc = 0; kc < 16; kc++) {
        if (kc < 15) { stageA(kc + 1, (kc + 1) & 1); stageW(w1t, kc + 1, (kc + 1) & 1);
                       CP_COMMIT(); CP_WAIT1(); }
        else CP_WAIT0();
        __syncthreads();
        int buf = kc & 1;
        mma_chunk16<true>(smu + AB + buf * 2048, 16, smu + WB + buf * 4096, 0,
                          lane, wm, wn, acc);
        __syncthreads();
    }

    // prefetch first L2 weight chunk, then h1 writeback
    stageW(w2t, 0, 0); CP_COMMIT();

    // h1 = fp16(relu(acc + b1)) -> HS (stride-132 half2 rows); reset acc
#pragma unroll
    for (int mi = 0; mi < 2; mi++) {
        int r = wm * 32 + mi * 16 + (lane >> 2);
#pragma unroll
        for (int ni = 0; ni < 8; ni++) {
            int n = wn * 64 + ni * 8 + 2 * (lane & 3);
            int ww = n >> 1;
            float c0 = smf[B1S + n], c1 = smf[B1S + n + 1];
            smu[HS + r * 132 + ww] =
                f2h2(fmaxf(acc[mi][ni][0] + c0, 0.f), fmaxf(acc[mi][ni][1] + c1, 0.f));
            smu[HS + (r + 8) * 132 + ww] =
                f2h2(fmaxf(acc[mi][ni][2] + c0, 0.f), fmaxf(acc[mi][ni][3] + c1, 0.f));
#pragma unroll
            for (int q = 0; q < 4; q++) acc[mi][ni][q] = 0.f;
        }
    }

    // ---- layer 2: K = 256 halves, A = HS resident, W double-buffered ----
    for (int kc = 0; kc < 8; kc++) {
        if (kc < 7) { stageW(w2t, kc + 1, (kc + 1) & 1); CP_COMMIT(); CP_WAIT1(); }
        else CP_WAIT0();
        __syncthreads();
        mma_chunk16<false>(smu + HS, 132, smu + WB + (kc & 1) * 4096, kc * 16,
                           lane, wm, wn, acc);
        __syncthreads();
    }

    // ---- h2 (fp32, registers) + layer-3 partials.
    // Each row's h2 lives in 16 threads (4 lanes x 4 wn-warps). Reduce the 4 lanes
    // of each quad FIRST via butterfly shuffle (fixed order: xor1 then xor2 —
    // deterministic), then lane&3==0 writes the (row, wn) slot. (R10 bug: all 4
    // lanes raced on one slot, dropping 3/4 of the sum.)
    {
        float p[2][2][3];
#pragma unroll
        for (int mi = 0; mi < 2; mi++)
#pragma unroll
            for (int h = 0; h < 2; h++)
#pragma unroll
                for (int o = 0; o < 3; o++) p[mi][h][o] = 0.f;
#pragma unroll
        for (int ni = 0; ni < 8; ni++) {
            int n = wn * 64 + ni * 8 + 2 * (lane & 3);
            float c0 = smf[B2S + n], c1 = smf[B2S + n + 1];
#pragma unroll
            for (int mi = 0; mi < 2; mi++) {
                float v00 = fmaxf(acc[mi][ni][0] + c0, 0.f);
                float v01 = fmaxf(acc[mi][ni][1] + c1, 0.f);
                float v10 = fmaxf(acc[mi][ni][2] + c0, 0.f);
                float v11 = fmaxf(acc[mi][ni][3] + c1, 0.f);
#pragma unroll
                for (int o = 0; o < 3; o++) {
                    if (o >= nout) break;
                    float w0 = smf[W3S + n * nout + o];
                    float w1v = smf[W3S + (n + 1) * nout + o];
                    p[mi][0][o] = fmaf(v00, w0, fmaf(v01, w1v, p[mi][0][o]));
                    p[mi][1][o] = fmaf(v10, w0, fmaf(v11, w1v, p[mi][1][o]));
                }
            }
        }
        // quad butterfly reduction (lanes 4g..4g+3 hold the same rows)
#pragma unroll
        for (int mi = 0; mi < 2; mi++)
#pragma unroll
            for (int h = 0; h < 2; h++)
#pragma unroll
                for (int o = 0; o < 3; o++) {
                    if (o >= nout) break;
                    float v = p[mi][h][o];
                    v += __shfl_xor_sync(0xFFFFFFFFu, v, 1);
                    v += __shfl_xor_sync(0xFFFFFFFFu, v, 2);
                    p[mi][h][o] = v;
                }
        if ((lane & 3) == 0) {
#pragma unroll
            for (int mi = 0; mi < 2; mi++)
#pragma unroll
                for (int h = 0; h < 2; h++) {
                    int row = wm * 32 + mi * 16 + (lane >> 2) + 8 * h;
#pragma unroll
                    for (int o = 0; o < 3; o++) {
                        if (o >= nout) break;
                        smf[RED + (row * 4 + wn) * 3 + o] = p[mi][h][o];
                    }
                }
        }
    }
    __syncthreads();
    if (tid < nrows) {
        size_t orow = (size_t)rid[tid];
#pragma unroll
        for (int o = 0; o < 3; o++) {
            if (o >= nout) break;
            float s = b3[o];
#pragma unroll
            for (int g = 0; g < 4; g++) s += smf[RED + (tid * 4 + g) * 3 + o];
            if (sig) s = 1.f / (1.f + expf(-s));
            obase[orow * nout + o] = s;
        }
    }
}

// ---------------- launch ----------------
extern "C" void kernel_launch(void* const* d_in, const int* in_sizes, int n_in,
                              void* d_out, int out_size) {
    const float* embedding = (const float*)d_in[0];
    const float* speed     = (const float*)d_in[1];
    const int*   command   = (const int*)d_in[2];
    const float* sw1 = (const float*)d_in[3];
    const float* sb1 = (const float*)d_in[4];
    const float* sw2 = (const float*)d_in[5];
    const float* sb2 = (const float*)d_in[6];
    const float* bw1 = (const float*)d_in[7];
    const float* bb1 = (const float*)d_in[8];
    const float* bw2 = (const float*)d_in[9];
    const float* bb2 = (const float*)d_in[10];
    const float* bw3 = (const float*)d_in[11];
    const float* bb3 = (const float*)d_in[12];
    const float* ow1 = (const float*)d_in[13];
    const float* ob1 = (const float*)d_in[14];
    const float* ow2 = (const float*)d_in[15];
    const float* ob2 = (const float*)d_in[16];
    const float* ow3 = (const float*)d_in[17];
    const float* ob3 = (const float*)d_in[18];
    float* out = (float*)d_out;

    const int SMEM_EMB = EMB_WORDS * 4;   // 102,912 B
    const int SMEM_MLP = MLP_WORDS * 4;   // 128,512 B
    cudaFuncSetAttribute((const void*)k_emb,
                         cudaFuncAttributeMaxDynamicSharedMemorySize, SMEM_EMB);
    cudaFuncSetAttribute((const void*)k_mlp,
                         cudaFuncAttributeMaxDynamicSharedMemorySize, SMEM_MLP);

    k_cvtw<<<736, 256>>>(sw2, bw1, bw2, ow1, ow2);
    k_hist<<<BATCH / 256, 256>>>(command);
    k_plan<<<1, 32>>>();
    k_scatter<<<BATCH / 256, 256>>>(command);
    k_emb<<<dim3(BATCH / 128, DD / 256), 512, SMEM_EMB>>>(embedding, speed, sw1, sb1, sb2);
    k_mlp<<<MAX_TILES + BATCH / TM, 512, SMEM_MLP>>>(bb1, bb2, bw3, bb3,
                                                     ob1, ob2, ow3, ob3, out);
}

// round 15
// speedup vs baseline: 5.5829x; 1.0480x over previous
#include <cuda_runtime.h>
#include <cuda_fp16.h>
#include <math.h>
#include <stdint.h>

#define BATCH 65536
#define DD 512
#define HH 256
#define NBR 6
#define TM 128
#define MAX_TILES (BATCH / TM + NBR)   // 518

// packed-half2 weight scratch, word offsets; per-chunk tiles [kc][n][16 words]
#define OFF_SW2T 0         // 8 kc x 512 n x 16
#define OFF_BW1  65536     // 6 x (16 kc x 256 x 16)
#define OFF_BW2  458752    // 6 x (8 kc x 256 x 16)
#define OFF_OW1  655360
#define OFF_OW2  720896
#define WT_TOTAL 753664

// ---- k_mlp smem word map ----
#define HS 0          // 128 x 132 (h1 half2)
#define WB 16896      // 3 x 4096  (W chunk bufs [256][16], XOR swizzle)
#define AB 29184      // 3 x 2048  (A chunk bufs [128][16], XOR swizzle)
#define B1S 35328     // 256
#define B2S 35584     // 256
#define W3S 35840     // 768
#define RED 36608     // 1536
#define RIDW 38144    // 128
#define MLP_WORDS 38272   // 153,088 B

// ---- k_emb smem word map ----
#define EA 0          // 128 x 132 (A half2, resident full K)
#define EW 16896      // 3 x 4096
#define ESP 29184     // 128
#define ESW1 29312    // 256
#define ESB1 29568    // 256
#define EMB_WORDS 29824   // 119,296 B

__device__ unsigned g_emb[(size_t)BATCH * 256];  // emb as packed half2 (64 MB)
__device__ unsigned g_wt[WT_TOTAL];
__device__ int g_idx[BATCH];
__device__ int g_counts[NBR];
__device__ int g_cursor[NBR];
__device__ int g_tb[MAX_TILES], g_ts[MAX_TILES], g_tr[MAX_TILES];
__device__ int g_ntiles;

// ---------------- helpers ----------------
__device__ __forceinline__ unsigned f2h2(float lo, float hi) {
    __half2 h = __floats2half2_rn(lo, hi);
    return *(unsigned*)&h;
}
__device__ __forceinline__ void cpa16(unsigned dst, const void* src) {
    asm volatile("cp.async.cg.shared.global [%0], [%1], 16;" :: "r"(dst), "l"(src) : "memory");
}
#define CP_COMMIT() asm volatile("cp.async.commit_group;" ::: "memory")
#define CP_WAIT0()  asm volatile("cp.async.wait_group 0;" ::: "memory")
#define CP_WAIT1()  asm volatile("cp.async.wait_group 1;" ::: "memory")

__device__ __forceinline__ void mma_f16(float* d, const uint32_t* a, const uint32_t* b) {
    asm volatile(
        "mma.sync.aligned.m16n8k16.row.col.f32.f16.f16.f32 "
        "{%0,%1,%2,%3},{%4,%5,%6,%7},{%8,%9},{%0,%1,%2,%3};"
        : "+f"(d[0]), "+f"(d[1]), "+f"(d[2]), "+f"(d[3])
        : "r"(a[0]), "r"(a[1]), "r"(a[2]), "r"(a[3]), "r"(b[0]), "r"(b[1]));
}
__device__ __forceinline__ void ldsm4(uint32_t* r, uint32_t addr) {
    asm volatile("ldmatrix.sync.aligned.m8n8.x4.shared.b16 {%0,%1,%2,%3}, [%4];"
                 : "=r"(r[0]), "=r"(r[1]), "=r"(r[2]), "=r"(r[3]) : "r"(addr));
}

// One K=32-half chunk, 128x256 block tile, 16 warps (warp tile 32x64), ldmatrix loads.
// offA/offB: per-lane byte offsets (precomputed); baseA/baseB: smem byte bases.
__device__ __forceinline__ void do_chunk(const unsigned offA[2][2], unsigned baseA,
                                         const unsigned offB[2][4], unsigned baseB,
                                         float acc[2][8][4]) {
#pragma unroll
    for (int ks = 0; ks < 2; ks++) {
        uint32_t a0[4], a1[4], bf[4][4];
        ldsm4(a0, baseA + offA[0][ks]);
        ldsm4(a1, baseA + offA[1][ks]);
#pragma unroll
        for (int nip = 0; nip < 4; nip++) ldsm4(bf[nip], baseB + offB[ks][nip]);
#pragma unroll
        for (int ni = 0; ni < 8; ni++) {
            const uint32_t* bp = &bf[ni >> 1][(ni & 1) * 2];
            mma_f16(acc[0][ni], a0, bp);
            mma_f16(acc[1][ni], a1, bp);
        }
    }
}

// ---------------- setup: coalesced convert+transpose, zero counts ----------------
__global__ void k_cvtw(const float* __restrict__ sw2, const float* __restrict__ bw1,
                       const float* __restrict__ bw2, const float* __restrict__ ow1,
                       const float* __restrict__ ow2) {
    __shared__ float s[32][65];
    int b = blockIdx.x, tid = threadIdx.x;
    const float* src; unsigned ob; int N, kc, n0;
    if (b < 64)       { src = sw2; N = 512; kc = b >> 3; n0 = (b & 7) * 64;
                        ob = OFF_SW2T + kc * 512 * 16; }
    else if (b < 448) { int r = b - 64; int m = r / 64; int rr = r % 64;
                        src = bw1 + (size_t)m * DD * HH; N = 256;
                        kc = rr >> 2; n0 = (rr & 3) * 64;
                        ob = OFF_BW1 + m * 65536u + kc * 256 * 16; }
    else if (b < 640) { int r = b - 448; int m = r / 32; int rr = r % 32;
                        src = bw2 + (size_t)m * HH * HH; N = 256;
                        kc = rr >> 2; n0 = (rr & 3) * 64;
                        ob = OFF_BW2 + m * 32768u + kc * 256 * 16; }
    else if (b < 704) { int r = b - 640; src = ow1; N = 256;
                        kc = r >> 2; n0 = (r & 3) * 64;
                        ob = OFF_OW1 + kc * 256 * 16; }
    else              { int r = b - 704; src = ow2; N = 256;
                        kc = r >> 2; n0 = (r & 3) * 64;
                        ob = OFF_OW2 + kc * 256 * 16; }
#pragma unroll
    for (int u = 0; u < 8; u++) {
        int idx = u * 256 + tid;
        int k = idx >> 6, n = idx & 63;
        s[k][n] = src[(size_t)(kc * 32 + k) * N + n0 + n];
    }
    __syncthreads();
    int n = tid >> 2, q = tid & 3, k8 = q * 8;
    uint4 o;
    o.x = f2h2(s[k8 + 0][n], s[k8 + 1][n]);
    o.y = f2h2(s[k8 + 2][n], s[k8 + 3][n]);
    o.z = f2h2(s[k8 + 4][n], s[k8 + 5][n]);
    o.w = f2h2(s[k8 + 6][n], s[k8 + 7][n]);
    ((uint4*)(g_wt + ob + (size_t)(n0 + n) * 16))[q] = o;
    if (b == 0 && tid < NBR) g_counts[tid] = 0;
}

// ---------------- bucketing (proven) ----------------
__global__ void k_hist(const int* __restrict__ cmd) {
    __shared__ int c[NBR];
    int t = threadIdx.x;
    if (t < NBR) c[t] = 0;
    __syncthreads();
    atomicAdd(&c[cmd[blockIdx.x * 256 + t] - 1], 1);
    __syncthreads();
    if (t < NBR) atomicAdd(&g_counts[t], c[t]);
}

__global__ void k_plan() {
    int l = threadIdx.x;
    int c[NBR], base[NBR], tp[NBR];
    int b = 0, t = 0;
#pragma unroll
    for (int n = 0; n < NBR; n++) {
        c[n] = g_counts[n]; base[n] = b; tp[n] = t;
        b += c[n]; t += (c[n] + TM - 1) / TM;
    }
    for (int tile = l; tile < t; tile += 32) {
        int n = 0;
        while (n < NBR - 1 && tile >= tp[n + 1]) n++;
        int loc = tile - tp[n];
        g_tb[tile] = n;
        g_ts[tile] = base[n] + loc * TM;
        int rem = c[n] - loc * TM;
        g_tr[tile] = rem < TM ? rem : TM;
    }
    if (l == 0) g_ntiles = t;
    if (l < NBR) g_cursor[l] = base[l];
}

__global__ void k_scatter(const int* __restrict__ cmd) {
    __shared__ int lc[NBR], lb[NBR];
    int t = threadIdx.x;
    if (t < NBR) lc[t] = 0;
    __syncthreads();
    int r = blockIdx.x * 256 + t;
    int b = cmd[r] - 1;
    int rank = atomicAdd(&lc[b], 1);
    __syncthreads();
    if (t < NBR) lb[t] = atomicAdd(&g_cursor[t], lc[t]);
    __syncthreads();
    g_idx[lb[b] + rank] = r;  // downstream math independent of permutation
}

// ---------------- emb = fp16(embedding + relu(speed*sw1+sb1) @ sw2 + sb2) ----------------
__global__ __launch_bounds__(512, 1) void k_emb(
    const float* __restrict__ embedding, const float* __restrict__ speed,
    const float* __restrict__ sw1, const float* __restrict__ sb1,
    const float* __restrict__ sb2) {
    extern __shared__ unsigned smu[];
    float* smf = (float*)smu;
    int tid = threadIdx.x, lane = tid & 31, w = tid >> 5;
    int wm = w & 3, wn = w >> 2;
    int row0 = blockIdx.x * 128, col0 = blockIdx.y * 256;
    unsigned sb = (unsigned)__cvta_generic_to_shared(smu);

    // per-lane ldmatrix offsets
    int mi3 = lane >> 3, li = lane & 7, kb = mi3 >> 1, hi8 = mi3 & 1;
    unsigned offH[2][2], offB[2][4];
#pragma unroll
    for (int mi = 0; mi < 2; mi++)
#pragma unroll
        for (int ks = 0; ks < 2; ks++) {
            int r = wm * 32 + mi * 16 + hi8 * 8 + li;
            offH[mi][ks] = (unsigned)(r * 132 + ks * 8 + kb * 4) * 4u;
        }
#pragma unroll
    for (int ks = 0; ks < 2; ks++)
#pragma unroll
        for (int nip = 0; nip < 4; nip++) {
            int n = wn * 64 + (nip * 2 + kb) * 8 + li;
            offB[ks][nip] =
                (unsigned)(n * 16 + ((ks * 8 + hi8 * 4) ^ (4 * ((n >> 1) & 3)))) * 4u;
        }

    if (tid < 128) smf[ESP + tid] = speed[row0 + tid];
    if (tid < 256) { smf[ESW1 + tid] = sw1[tid]; smf[ESB1 + tid] = sb1[tid]; }
    __syncthreads();

    auto stageW = [&](int kc, int buf) {
#pragma unroll
        for (int u = 0; u < 2; u++) {
            int idx = u * 512 + tid;          // 1024 uint4
            int n = idx >> 2, q = idx & 3;
            cpa16(sb + (unsigned)(EW + buf * 4096 + n * 16 +
                                  ((q * 4) ^ (4 * ((n >> 1) & 3)))) * 4u,
                  g_wt + OFF_SW2T + (size_t)kc * 8192 + (size_t)(col0 + n) * 16 + q * 4);
        }
    };

    stageW(0, 0); CP_COMMIT();
    stageW(1, 1); CP_COMMIT();
    // build A = relu(speed*sw1+sb1) as half2, stride-132 rows
    for (int u = 0; u < 32; u++) {
        int idx = u * 512 + tid;
        int r = idx >> 7, ww = idx & 127;
        float v0 = fmaxf(fmaf(smf[ESP + r], smf[ESW1 + 2 * ww], smf[ESB1 + 2 * ww]), 0.f);
        float v1 = fmaxf(fmaf(smf[ESP + r], smf[ESW1 + 2 * ww + 1], smf[ESB1 + 2 * ww + 1]), 0.f);
        smu[EA + r * 132 + ww] = f2h2(v0, v1);
    }

    float acc[2][8][4];
#pragma unroll
    for (int i = 0; i < 2; i++)
#pragma unroll
        for (int j = 0; j < 8; j++)
#pragma unroll
            for (int q = 0; q < 4; q++) acc[i][j][q] = 0.f;

#pragma unroll 1
    for (int kc = 0; kc < 8; kc++) {
        if (kc == 7) CP_WAIT0(); else CP_WAIT1();
        __syncthreads();
        if (kc < 6) { stageW(kc + 2, (kc + 2) % 3); CP_COMMIT(); }
        do_chunk(offH, sb + (unsigned)(EA * 4 + kc * 64),
                 offB, sb + (unsigned)(EW + (kc % 3) * 4096) * 4u, acc);
    }

#pragma unroll
    for (int mi = 0; mi < 2; mi++) {
        int r = row0 + wm * 32 + mi * 16 + (lane >> 2);
#pragma unroll
        for (int ni = 0; ni < 8; ni++) {
            int n = col0 + wn * 64 + ni * 8 + 2 * (lane & 3);
            float s0 = sb2[n], s1 = sb2[n + 1];
            {
                float2 e = *(const float2*)&embedding[(size_t)r * DD + n];
                g_emb[(size_t)r * 256 + (n >> 1)] =
                    f2h2(acc[mi][ni][0] + e.x + s0, acc[mi][ni][1] + e.y + s1);
            }
            {
                float2 e = *(const float2*)&embedding[(size_t)(r + 8) * DD + n];
                g_emb[(size_t)(r + 8) * 256 + (n >> 1)] =
                    f2h2(acc[mi][ni][2] + e.x + s0, acc[mi][ni][3] + e.y + s1);
            }
        }
    }
}

// ---------------- fused 3-layer MLP (fp16 mma + ldmatrix, both heads) ----------------
__global__ __launch_bounds__(512, 1) void k_mlp(
    const float* __restrict__ bb1, const float* __restrict__ bb2,
    const float* __restrict__ bw3, const float* __restrict__ bb3,
    const float* __restrict__ ob1, const float* __restrict__ ob2,
    const float* __restrict__ ow3, const float* __restrict__ ob3,
    float* __restrict__ out) {
    extern __shared__ unsigned smu[];
    float* smf = (float*)smu;
    int tid = threadIdx.x, lane = tid & 31, w = tid >> 5;
    int wm = w & 3, wn = w >> 2;
    int bid = blockIdx.x;
    unsigned sb = (unsigned)__cvta_generic_to_shared(smu);

    const unsigned *w1t, *w2t;
    const float *w3, *b1, *b2, *b3;
    float* obase;
    int nout, start, nrows;
    bool sig, gather;
    if (bid < MAX_TILES) {
        if (bid >= g_ntiles) return;
        int nb = g_tb[bid]; start = g_ts[bid]; nrows = g_tr[bid];
        w1t = g_wt + OFF_BW1 + (size_t)nb * 65536;
        w2t = g_wt + OFF_BW2 + (size_t)nb * 32768;
        w3 = bw3 + nb * HH * 3; b1 = bb1 + nb * HH; b2 = bb2 + nb * HH; b3 = bb3 + nb * 3;
        nout = 3; sig = true; obase = out; gather = true;
    } else {
        start = (bid - MAX_TILES) * TM; nrows = TM;
        w1t = g_wt + OFF_OW1; w2t = g_wt + OFF_OW2;
        w3 = ow3; b1 = ob1; b2 = ob2; b3 = ob3;
        nout = 1; sig = false; obase = out + (size_t)3 * BATCH; gather = false;
    }
    if (tid < TM) {
        int i = (tid < nrows) ? tid : (nrows - 1);  // clamp pads; stores guarded
        ((int*)(smu + RIDW))[tid] = gather ? g_idx[start + i] : (start + i);
    }
    if (tid < 256) { smf[B1S + tid] = b1[tid]; smf[B2S + tid] = b2[tid]; }
    for (int idx = tid; idx < HH * nout; idx += 512) smf[W3S + idx] = w3[idx];
    __syncthreads();
    const int* rid = (const int*)(smu + RIDW);

    // per-lane ldmatrix offsets
    int mi3 = lane >> 3, li = lane & 7, kb = mi3 >> 1, hi8 = mi3 & 1;
    unsigned offA[2][2], offH[2][2], offB[2][4];
#pragma unroll
    for (int mi = 0; mi < 2; mi++)
#pragma unroll
        for (int ks = 0; ks < 2; ks++) {
            int r = wm * 32 + mi * 16 + hi8 * 8 + li;
            offA[mi][ks] =
                (unsigned)(r * 16 + ((ks * 8 + kb * 4) ^ (4 * ((r >> 1) & 3)))) * 4u;
            offH[mi][ks] = (unsigned)(r * 132 + ks * 8 + kb * 4) * 4u;
        }
#pragma unroll
    for (int ks = 0; ks < 2; ks++)
#pragma unroll
        for (int nip = 0; nip < 4; nip++) {
            int n = wn * 64 + (nip * 2 + kb) * 8 + li;
            offB[ks][nip] =
                (unsigned)(n * 16 + ((ks * 8 + hi8 * 4) ^ (4 * ((n >> 1) & 3)))) * 4u;
        }

    auto stageA = [&](int kc, int buf) {
        int r = tid >> 2, q = tid & 3;  // 512 uint4
        cpa16(sb + (unsigned)(AB + buf * 2048 + r * 16 +
                              ((q * 4) ^ (4 * ((r >> 1) & 3)))) * 4u,
              g_emb + (size_t)rid[r] * 256 + kc * 16 + q * 4);
    };
    auto stageW = [&](const unsigned* wt, int kc, int buf) {
#pragma unroll
        for (int u = 0; u < 2; u++) {
            int idx = u * 512 + tid;
            int n = idx >> 2, q = idx & 3;
            cpa16(sb + (unsigned)(WB + buf * 4096 + n * 16 +
                                  ((q * 4) ^ (4 * ((n >> 1) & 3)))) * 4u,
                  wt + (size_t)kc * 4096 + n * 16 + q * 4);
        }
    };

    float acc[2][8][4];
#pragma unroll
    for (int i = 0; i < 2; i++)
#pragma unroll
        for (int j = 0; j < 8; j++)
#pragma unroll
            for (int q = 0; q < 4; q++) acc[i][j][q] = 0.f;

    // ---- layer 1: K = 512 halves, 16 chunks; 3 bufs, 1 sync/chunk ----
    stageA(0, 0); stageW(w1t, 0, 0); CP_COMMIT();
    stageA(1, 1); stageW(w1t, 1, 1); CP_COMMIT();
#pragma unroll 1
    for (int kc = 0; kc < 16; kc++) {
        CP_WAIT1();
        __syncthreads();
        if (kc < 14) {
            int nb = (kc + 2) % 3;
            stageA(kc + 2, nb); stageW(w1t, kc + 2, nb); CP_COMMIT();
        } else if (kc == 14) { stageW(w2t, 0, 1); CP_COMMIT(); }  // L2 prefetch into buf 1
        else                 { stageW(w2t, 1, 2); CP_COMMIT(); }  // buf 2
        int buf = kc % 3;
        do_chunk(offA, sb + (unsigned)(AB + buf * 2048) * 4u,
                 offB, sb + (unsigned)(WB + buf * 4096) * 4u, acc);
    }

    // h1 = fp16(relu(acc + b1)) -> HS; reset acc (sync at L2 iter0 publishes HS)
#pragma unroll
    for (int mi = 0; mi < 2; mi++) {
        int r = wm * 32 + mi * 16 + (lane >> 2);
#pragma unroll
        for (int ni = 0; ni < 8; ni++) {
            int n = wn * 64 + ni * 8 + 2 * (lane & 3);
            int ww = n >> 1;
            float c0 = smf[B1S + n], c1 = smf[B1S + n + 1];
            smu[HS + r * 132 + ww] =
                f2h2(fmaxf(acc[mi][ni][0] + c0, 0.f), fmaxf(acc[mi][ni][1] + c1, 0.f));
            smu[HS + (r + 8) * 132 + ww] =
                f2h2(fmaxf(acc[mi][ni][2] + c0, 0.f), fmaxf(acc[mi][ni][3] + c1, 0.f));
#pragma unroll
            for (int q = 0; q < 4; q++) acc[mi][ni][q] = 0.f;
        }
    }

    // ---- layer 2: K = 256 halves, A = HS resident; chunk kc2 lives in buf (kc2+1)%3 ----
#pragma unroll 1
    for (int kc2 = 0; kc2 < 8; kc2++) {
        if (kc2 == 7) CP_WAIT0(); else CP_WAIT1();
        __syncthreads();
        if (kc2 < 6) { stageW(w2t, kc2 + 2, kc2 % 3); CP_COMMIT(); }
        int buf = (kc2 + 1) % 3;
        do_chunk(offH, sb + (unsigned)(HS * 4 + kc2 * 64),
                 offB, sb + (unsigned)(WB + buf * 4096) * 4u, acc);
    }

    // ---- h2 (fp32 regs) + layer-3 partials; quad butterfly (xor1,xor2: fixed order) ----
    {
        float p[2][2][3];
#pragma unroll
        for (int mi = 0; mi < 2; mi++)
#pragma unroll
            for (int h = 0; h < 2; h++)
#pragma unroll
                for (int o = 0; o < 3; o++) p[mi][h][o] = 0.f;
#pragma unroll
        for (int ni = 0; ni < 8; ni++) {
            int n = wn * 64 + ni * 8 + 2 * (lane & 3);
            float c0 = smf[B2S + n], c1 = smf[B2S + n + 1];
#pragma unroll
            for (int mi = 0; mi < 2; mi++) {
                float v00 = fmaxf(acc[mi][ni][0] + c0, 0.f);
                float v01 = fmaxf(acc[mi][ni][1] + c1, 0.f);
                float v10 = fmaxf(acc[mi][ni][2] + c0, 0.f);
                float v11 = fmaxf(acc[mi][ni][3] + c1, 0.f);
#pragma unroll
                for (int o = 0; o < 3; o++) {
                    if (o >= nout) break;
                    float w0 = smf[W3S + n * nout + o];
                    float w1v = smf[W3S + (n + 1) * nout + o];
                    p[mi][0][o] = fmaf(v00, w0, fmaf(v01, w1v, p[mi][0][o]));
                    p[mi][1][o] = fmaf(v10, w0, fmaf(v11, w1v, p[mi][1][o]));
                }
            }
        }
#pragma unroll
        for (int mi = 0; mi < 2; mi++)
#pragma unroll
            for (int h = 0; h < 2; h++)
#pragma unroll
                for (int o = 0; o < 3; o++) {
                    if (o >= nout) break;
                    float v = p[mi][h][o];
                    v += __shfl_xor_sync(0xFFFFFFFFu, v, 1);
                    v += __shfl_xor_sync(0xFFFFFFFFu, v, 2);
                    p[mi][h][o] = v;
                }
        if ((lane & 3) == 0) {
#pragma unroll
            for (int mi = 0; mi < 2; mi++)
#pragma unroll
                for (int h = 0; h < 2; h++) {
                    int row = wm * 32 + mi * 16 + (lane >> 2) + 8 * h;
#pragma unroll
                    for (int o = 0; o < 3; o++) {
                        if (o >= nout) break;
                        smf[RED + (row * 4 + wn) * 3 + o] = p[mi][h][o];
                    }
                }
        }
    }
    __syncthreads();
    if (tid < nrows) {
        size_t orow = (size_t)rid[tid];
#pragma unroll
        for (int o = 0; o < 3; o++) {
            if (o >= nout) break;
            float s = b3[o];
#pragma unroll
            for (int g = 0; g < 4; g++) s += smf[RED + (tid * 4 + g) * 3 + o];
            if (sig) s = 1.f / (1.f + expf(-s));
            obase[orow * nout + o] = s;
        }
    }
}

// ---------------- launch ----------------
extern "C" void kernel_launch(void* const* d_in, const int* in_sizes, int n_in,
                              void* d_out, int out_size) {
    const float* embedding = (const float*)d_in[0];
    const float* speed     = (const float*)d_in[1];
    const int*   command   = (const int*)d_in[2];
    const float* sw1 = (const float*)d_in[3];
    const float* sb1 = (const float*)d_in[4];
    const float* sw2 = (const float*)d_in[5];
    const float* sb2 = (const float*)d_in[6];
    const float* bw1 = (const float*)d_in[7];
    const float* bb1 = (const float*)d_in[8];
    const float* bw2 = (const float*)d_in[9];
    const float* bb2 = (const float*)d_in[10];
    const float* bw3 = (const float*)d_in[11];
    const float* bb3 = (const float*)d_in[12];
    const float* ow1 = (const float*)d_in[13];
    const float* ob1 = (const float*)d_in[14];
    const float* ow2 = (const float*)d_in[15];
    const float* ob2 = (const float*)d_in[16];
    const float* ow3 = (const float*)d_in[17];
    const float* ob3 = (const float*)d_in[18];
    float* out = (float*)d_out;

    const int SMEM_EMB = EMB_WORDS * 4;   // 119,296 B
    const int SMEM_MLP = MLP_WORDS * 4;   // 153,088 B
    cudaFuncSetAttribute((const void*)k_emb,
                         cudaFuncAttributeMaxDynamicSharedMemorySize, SMEM_EMB);
    cudaFuncSetAttribute((const void*)k_mlp,
                         cudaFuncAttributeMaxDynamicSharedMemorySize, SMEM_MLP);

    k_cvtw<<<736, 256>>>(sw2, bw1, bw2, ow1, ow2);
    k_hist<<<BATCH / 256, 256>>>(command);
    k_plan<<<1, 32>>>();
    k_scatter<<<BATCH / 256, 256>>>(command);
    k_emb<<<dim3(BATCH / 128, DD / 256), 512, SMEM_EMB>>>(embedding, speed, sw1, sb1, sb2);
    k_mlp<<<MAX_TILES + BATCH / TM, 512, SMEM_MLP>>>(bb1, bb2, bw3, bb3,
                                                     ob1, ob2, ow3, ob3, out);
}

// round 17
// speedup vs baseline: 5.7961x; 1.0382x over previous
#include <cuda_runtime.h>
#include <cuda_fp16.h>
#include <math.h>
#include <stdint.h>

#define BATCH 65536
#define DD 512
#define HH 256
#define NBR 6
#define TM 128
#define MAX_TILES (BATCH / TM + NBR)   // 518

// packed-half2 weight scratch, word offsets; per-chunk tiles [kc][n][16 words]
#define OFF_SW2T 0         // 8 kc x 512 n x 16
#define OFF_BW1  65536     // 6 x (16 kc x 256 x 16)
#define OFF_BW2  458752    // 6 x (8 kc x 256 x 16)
#define OFF_OW1  655360
#define OFF_OW2  720896
#define WT_TOTAL 753664

// ---- k_mlp smem word map (4-buffer pipeline) ----
#define HS 0          // 128 x 132 (h1 half2)
#define WB 16896      // 4 x 4096  (W chunk bufs [256][16], XOR swizzle)
#define AB 33280      // 4 x 2048  (A chunk bufs [128][16], XOR swizzle)
#define B1S 41472     // 256
#define B2S 41728     // 256
#define W3S 41984     // 768
#define RED 42752     // 1536
#define RIDW 44288    // 128
#define MLP_WORDS 44416   // 177,664 B

// ---- k_emb smem word map ----
#define EA 0          // 128 x 132 (A half2, resident full K)
#define EW 16896      // 4 x 4096
#define ESP 33280     // 128
#define ESW1 33408    // 256
#define ESB1 33664    // 256
#define EMB_WORDS 33920   // 135,680 B

__device__ unsigned g_emb[(size_t)BATCH * 256];  // emb as packed half2 (64 MB)
__device__ unsigned g_wt[WT_TOTAL];
__device__ int g_idx[BATCH];
__device__ int g_counts[NBR];                    // zero at load; k_plan re-zeros per launch
__device__ int g_cursor[NBR];
__device__ int g_tb[MAX_TILES], g_ts[MAX_TILES], g_tr[MAX_TILES];
__device__ int g_ntiles;

// ---------------- helpers ----------------
__device__ __forceinline__ unsigned f2h2(float lo, float hi) {
    __half2 h = __floats2half2_rn(lo, hi);
    return *(unsigned*)&h;
}
__device__ __forceinline__ void cpa16(unsigned dst, const void* src) {
    asm volatile("cp.async.cg.shared.global [%0], [%1], 16;" :: "r"(dst), "l"(src) : "memory");
}
#define CP_COMMIT() asm volatile("cp.async.commit_group;" ::: "memory")
#define CP_WAIT0()  asm volatile("cp.async.wait_group 0;" ::: "memory")
#define CP_WAIT1()  asm volatile("cp.async.wait_group 1;" ::: "memory")
#define CP_WAIT2()  asm volatile("cp.async.wait_group 2;" ::: "memory")

__device__ __forceinline__ void mma_f16(float* d, const uint32_t* a, const uint32_t* b) {
    asm volatile(
        "mma.sync.aligned.m16n8k16.row.col.f32.f16.f16.f32 "
        "{%0,%1,%2,%3},{%4,%5,%6,%7},{%8,%9},{%0,%1,%2,%3};"
        : "+f"(d[0]), "+f"(d[1]), "+f"(d[2]), "+f"(d[3])
        : "r"(a[0]), "r"(a[1]), "r"(a[2]), "r"(a[3]), "r"(b[0]), "r"(b[1]));
}
__device__ __forceinline__ void ldsm4(uint32_t* r, uint32_t addr) {
    asm volatile("ldmatrix.sync.aligned.m8n8.x4.shared.b16 {%0,%1,%2,%3}, [%4];"
                 : "=r"(r[0]), "=r"(r[1]), "=r"(r[2]), "=r"(r[3]) : "r"(addr));
}

// One K=32-half chunk, 128x256 block tile, 16 warps (warp tile 32x64), ldmatrix loads.
__device__ __forceinline__ void do_chunk(const unsigned offA[2][2], unsigned baseA,
                                         const unsigned offB[2][4], unsigned baseB,
                                         float acc[2][8][4]) {
#pragma unroll
    for (int ks = 0; ks < 2; ks++) {
        uint32_t a0[4], a1[4], bf[4][4];
        ldsm4(a0, baseA + offA[0][ks]);
        ldsm4(a1, baseA + offA[1][ks]);
#pragma unroll
        for (int nip = 0; nip < 4; nip++) ldsm4(bf[nip], baseB + offB[ks][nip]);
#pragma unroll
        for (int ni = 0; ni < 8; ni++) {
            const uint32_t* bp = &bf[ni >> 1][(ni & 1) * 2];
            mma_f16(acc[0][ni], a0, bp);
            mma_f16(acc[1][ni], a1, bp);
        }
    }
}

// ---------------- setup: coalesced convert+transpose, + histogram (blocks 0..255) ----------------
__global__ void k_cvtw(const float* __restrict__ sw2, const float* __restrict__ bw1,
                       const float* __restrict__ bw2, const float* __restrict__ ow1,
                       const float* __restrict__ ow2, const int* __restrict__ cmd) {
    __shared__ float s[32][65];
    __shared__ int c[NBR];
    int b = blockIdx.x, tid = threadIdx.x;
    if (tid < NBR) c[tid] = 0;
    const float* src; unsigned ob; int N, kc, n0;
    if (b < 64)       { src = sw2; N = 512; kc = b >> 3; n0 = (b & 7) * 64;
                        ob = OFF_SW2T + kc * 512 * 16; }
    else if (b < 448) { int r = b - 64; int m = r / 64; int rr = r % 64;
                        src = bw1 + (size_t)m * DD * HH; N = 256;
                        kc = rr >> 2; n0 = (rr & 3) * 64;
                        ob = OFF_BW1 + m * 65536u + kc * 256 * 16; }
    else if (b < 640) { int r = b - 448; int m = r / 32; int rr = r % 32;
                        src = bw2 + (size_t)m * HH * HH; N = 256;
                        kc = rr >> 2; n0 = (rr & 3) * 64;
                        ob = OFF_BW2 + m * 32768u + kc * 256 * 16; }
    else if (b < 704) { int r = b - 640; src = ow1; N = 256;
                        kc = r >> 2; n0 = (r & 3) * 64;
                        ob = OFF_OW1 + kc * 256 * 16; }
    else              { int r = b - 704; src = ow2; N = 256;
                        kc = r >> 2; n0 = (r & 3) * 64;
                        ob = OFF_OW2 + kc * 256 * 16; }
#pragma unroll
    for (int u = 0; u < 8; u++) {
        int idx = u * 256 + tid;
        int k = idx >> 6, n = idx & 63;
        s[k][n] = src[(size_t)(kc * 32 + k) * N + n0 + n];
    }
    __syncthreads();             // c zeroed + s filled
    if (b < 256) atomicAdd(&c[cmd[b * 256 + tid] - 1], 1);
    __syncthreads();
    if (b < 256 && tid < NBR) atomicAdd(&g_counts[tid], c[tid]);
    int n = tid >> 2, q = tid & 3, k8 = q * 8;
    uint4 o;
    o.x = f2h2(s[k8 + 0][n], s[k8 + 1][n]);
    o.y = f2h2(s[k8 + 2][n], s[k8 + 3][n]);
    o.z = f2h2(s[k8 + 4][n], s[k8 + 5][n]);
    o.w = f2h2(s[k8 + 6][n], s[k8 + 7][n]);
    ((uint4*)(g_wt + ob + (size_t)(n0 + n) * 16))[q] = o;
}

// ---------------- plan (resets g_counts for next replay) + scatter ----------------
__global__ void k_plan() {
    int l = threadIdx.x;
    int c[NBR], base[NBR], tp[NBR];
    int b = 0, t = 0;
#pragma unroll
    for (int n = 0; n < NBR; n++) {
        c[n] = g_counts[n]; base[n] = b; tp[n] = t;
        b += c[n]; t += (c[n] + TM - 1) / TM;
    }
    for (int tile = l; tile < t; tile += 32) {
        int n = 0;
        while (n < NBR - 1 && tile >= tp[n + 1]) n++;
        int loc = tile - tp[n];
        g_tb[tile] = n;
        g_ts[tile] = base[n] + loc * TM;
        int rem = c[n] - loc * TM;
        g_tr[tile] = rem < TM ? rem : TM;
    }
    if (l == 0) g_ntiles = t;
    if (l < NBR) { g_cursor[l] = base[l]; g_counts[l] = 0; }  // reset for next replay
}

__global__ void k_scatter(const int* __restrict__ cmd) {
    __shared__ int lc[NBR], lb[NBR];
    int t = threadIdx.x;
    if (t < NBR) lc[t] = 0;
    __syncthreads();
    int r = blockIdx.x * 512 + t;
    int b = cmd[r] - 1;
    int rank = atomicAdd(&lc[b], 1);
    __syncthreads();
    if (t < NBR) lb[t] = atomicAdd(&g_cursor[t], lc[t]);
    __syncthreads();
    g_idx[lb[b] + rank] = r;  // downstream math independent of permutation
}

// ---------------- emb = fp16(embedding + relu(speed*sw1+sb1) @ sw2 + sb2) ----------------
__global__ __launch_bounds__(512, 1) void k_emb(
    const float* __restrict__ embedding, const float* __restrict__ speed,
    const float* __restrict__ sw1, const float* __restrict__ sb1,
    const float* __restrict__ sb2) {
    extern __shared__ unsigned smu[];
    float* smf = (float*)smu;
    int tid = threadIdx.x, lane = tid & 31, w = tid >> 5;
    int wm = w & 3, wn = w >> 2;
    int row0 = blockIdx.x * 128, col0 = blockIdx.y * 256;
    unsigned sb = (unsigned)__cvta_generic_to_shared(smu);

    int mi3 = lane >> 3, li = lane & 7, kb = mi3 >> 1, hi8 = mi3 & 1;
    unsigned offH[2][2], offB[2][4];
#pragma unroll
    for (int mi = 0; mi < 2; mi++)
#pragma unroll
        for (int ks = 0; ks < 2; ks++) {
            int r = wm * 32 + mi * 16 + hi8 * 8 + li;
            offH[mi][ks] = (unsigned)(r * 132 + ks * 8 + kb * 4) * 4u;
        }
#pragma unroll
    for (int ks = 0; ks < 2; ks++)
#pragma unroll
        for (int nip = 0; nip < 4; nip++) {
            int n = wn * 64 + (nip * 2 + kb) * 8 + li;
            offB[ks][nip] =
                (unsigned)(n * 16 + ((ks * 8 + hi8 * 4) ^ (4 * ((n >> 1) & 3)))) * 4u;
        }

    if (tid < 128) smf[ESP + tid] = speed[row0 + tid];
    if (tid < 256) { smf[ESW1 + tid] = sw1[tid]; smf[ESB1 + tid] = sb1[tid]; }
    __syncthreads();

    auto stageW = [&](int kc, int buf) {
#pragma unroll
        for (int u = 0; u < 2; u++) {
            int idx = u * 512 + tid;          // 1024 uint4
            int n = idx >> 2, q = idx & 3;
            cpa16(sb + (unsigned)(EW + buf * 4096 + n * 16 +
                                  ((q * 4) ^ (4 * ((n >> 1) & 3)))) * 4u,
                  g_wt + OFF_SW2T + (size_t)kc * 8192 + (size_t)(col0 + n) * 16 + q * 4);
        }
    };

    stageW(0, 0); CP_COMMIT();
    stageW(1, 1); CP_COMMIT();
    // build A = relu(speed*sw1+sb1) as half2, stride-132 rows
    for (int u = 0; u < 32; u++) {
        int idx = u * 512 + tid;
        int r = idx >> 7, ww = idx & 127;
        float v0 = fmaxf(fmaf(smf[ESP + r], smf[ESW1 + 2 * ww], smf[ESB1 + 2 * ww]), 0.f);
        float v1 = fmaxf(fmaf(smf[ESP + r], smf[ESW1 + 2 * ww + 1], smf[ESB1 + 2 * ww + 1]), 0.f);
        smu[EA + r * 132 + ww] = f2h2(v0, v1);
    }

    float acc[2][8][4];
#pragma unroll
    for (int i = 0; i < 2; i++)
#pragma unroll
        for (int j = 0; j < 8; j++)
#pragma unroll
            for (int q = 0; q < 4; q++) acc[i][j][q] = 0.f;

    // 4-buf pipeline: stage kc+2 BEFORE barrier (prev user kc-2 done at barrier kc-1)
#pragma unroll 1
    for (int kc = 0; kc < 8; kc++) {
        if (kc < 6) { stageW(kc + 2, (kc + 2) & 3); CP_COMMIT(); }
        if (kc < 6) CP_WAIT2(); else if (kc == 6) CP_WAIT1(); else CP_WAIT0();
        __syncthreads();
        do_chunk(offH, sb + (unsigned)(kc * 64),
                 offB, sb + (unsigned)(EW + (kc & 3) * 4096) * 4u, acc);
    }

#pragma unroll
    for (int mi = 0; mi < 2; mi++) {
        int r = row0 + wm * 32 + mi * 16 + (lane >> 2);
#pragma unroll
        for (int ni = 0; ni < 8; ni++) {
            int n = col0 + wn * 64 + ni * 8 + 2 * (lane & 3);
            float s0 = sb2[n], s1 = sb2[n + 1];
            {
                float2 e = *(const float2*)&embedding[(size_t)r * DD + n];
                g_emb[(size_t)r * 256 + (n >> 1)] =
                    f2h2(acc[mi][ni][0] + e.x + s0, acc[mi][ni][1] + e.y + s1);
            }
            {
                float2 e = *(const float2*)&embedding[(size_t)(r + 8) * DD + n];
                g_emb[(size_t)(r + 8) * 256 + (n >> 1)] =
                    f2h2(acc[mi][ni][2] + e.x + s0, acc[mi][ni][3] + e.y + s1);
            }
        }
    }
}

// ---------------- fused 3-layer MLP (fp16 mma + ldmatrix, both heads) ----------------
__global__ __launch_bounds__(512, 1) void k_mlp(
    const float* __restrict__ bb1, const float* __restrict__ bb2,
    const float* __restrict__ bw3, const float* __restrict__ bb3,
    const float* __restrict__ ob1, const float* __restrict__ ob2,
    const float* __restrict__ ow3, const float* __restrict__ ob3,
    float* __restrict__ out) {
    extern __shared__ unsigned smu[];
    float* smf = (float*)smu;
    int tid = threadIdx.x, lane = tid & 31, w = tid >> 5;
    int wm = w & 3, wn = w >> 2;
    int bid = blockIdx.x;
    unsigned sb = (unsigned)__cvta_generic_to_shared(smu);

    const unsigned *w1t, *w2t;
    const float *w3, *b1, *b2, *b3;
    float* obase;
    int nout, start, nrows;
    bool sig, gather;
    if (bid < MAX_TILES) {
        if (bid >= g_ntiles) return;
        int nb = g_tb[bid]; start = g_ts[bid]; nrows = g_tr[bid];
        w1t = g_wt + OFF_BW1 + (size_t)nb * 65536;
        w2t = g_wt + OFF_BW2 + (size_t)nb * 32768;
        w3 = bw3 + nb * HH * 3; b1 = bb1 + nb * HH; b2 = bb2 + nb * HH; b3 = bb3 + nb * 3;
        nout = 3; sig = true; obase = out; gather = true;
    } else {
        start = (bid - MAX_TILES) * TM; nrows = TM;
        w1t = g_wt + OFF_OW1; w2t = g_wt + OFF_OW2;
        w3 = ow3; b1 = ob1; b2 = ob2; b3 = ob3;
        nout = 1; sig = false; obase = out + (size_t)3 * BATCH; gather = false;
    }
    if (tid < TM) {
        int i = (tid < nrows) ? tid : (nrows - 1);  // clamp pads; stores guarded
        ((int*)(smu + RIDW))[tid] = gather ? g_idx[start + i] : (start + i);
    }
    if (tid < 256) { smf[B1S + tid] = b1[tid]; smf[B2S + tid] = b2[tid]; }
    for (int idx = tid; idx < HH * nout; idx += 512) smf[W3S + idx] = w3[idx];
    __syncthreads();
    const int* rid = (const int*)(smu + RIDW);

    int mi3 = lane >> 3, li = lane & 7, kb = mi3 >> 1, hi8 = mi3 & 1;
    unsigned offA[2][2], offH[2][2], offB[2][4];
#pragma unroll
    for (int mi = 0; mi < 2; mi++)
#pragma unroll
        for (int ks = 0; ks < 2; ks++) {
            int r = wm * 32 + mi * 16 + hi8 * 8 + li;
            offA[mi][ks] =
                (unsigned)(r * 16 + ((ks * 8 + kb * 4) ^ (4 * ((r >> 1) & 3)))) * 4u;
            offH[mi][ks] = (unsigned)(r * 132 + ks * 8 + kb * 4) * 4u;
        }
#pragma unroll
    for (int ks = 0; ks < 2; ks++)
#pragma unroll
        for (int nip = 0; nip < 4; nip++) {
            int n = wn * 64 + (nip * 2 + kb) * 8 + li;
            offB[ks][nip] =
                (unsigned)(n * 16 + ((ks * 8 + hi8 * 4) ^ (4 * ((n >> 1) & 3)))) * 4u;
        }

    auto stageA = [&](int kc, int buf) {
        int r = tid >> 2, q = tid & 3;  // 512 uint4
        cpa16(sb + (unsigned)(AB + buf * 2048 + r * 16 +
                              ((q * 4) ^ (4 * ((r >> 1) & 3)))) * 4u,
              g_emb + (size_t)rid[r] * 256 + kc * 16 + q * 4);
    };
    auto stageW = [&](const unsigned* wt, int kc, int buf) {
#pragma unroll
        for (int u = 0; u < 2; u++) {
            int idx = u * 512 + tid;
            int n = idx >> 2, q = idx & 3;
            cpa16(sb + (unsigned)(WB + buf * 4096 + n * 16 +
                                  ((q * 4) ^ (4 * ((n >> 1) & 3)))) * 4u,
                  wt + (size_t)kc * 4096 + n * 16 + q * 4);
        }
    };

    float acc[2][8][4];
#pragma unroll
    for (int i = 0; i < 2; i++)
#pragma unroll
        for (int j = 0; j < 8; j++)
#pragma unroll
            for (int q = 0; q < 4; q++) acc[i][j][q] = 0.f;

    // ---- layer 1: K = 512 halves, 16 chunks; 4 bufs, stage-before-barrier ----
    stageA(0, 0); stageW(w1t, 0, 0); CP_COMMIT();
    stageA(1, 1); stageW(w1t, 1, 1); CP_COMMIT();
#pragma unroll 1
    for (int kc = 0; kc < 16; kc++) {
        if (kc < 14) {
            int nb4 = (kc + 2) & 3;
            stageA(kc + 2, nb4); stageW(w1t, kc + 2, nb4); CP_COMMIT();
        } else if (kc == 14) { stageW(w2t, 0, 0); CP_COMMIT(); }  // L2 chunk0 -> buf 0
        else                 { stageW(w2t, 1, 1); CP_COMMIT(); }  // L2 chunk1 -> buf 1
        CP_WAIT2();
        __syncthreads();
        int buf = kc & 3;
        do_chunk(offA, sb + (unsigned)(AB + buf * 2048) * 4u,
                 offB, sb + (unsigned)(WB + buf * 4096) * 4u, acc);
    }

    // h1 = fp16(relu(acc + b1)) -> HS; reset acc (L2 iter0's barrier publishes HS)
#pragma unroll
    for (int mi = 0; mi < 2; mi++) {
        int r = wm * 32 + mi * 16 + (lane >> 2);
#pragma unroll
        for (int ni = 0; ni < 8; ni++) {
            int n = wn * 64 + ni * 8 + 2 * (lane & 3);
            int ww = n >> 1;
            float c0 = smf[B1S + n], c1 = smf[B1S + n + 1];
            smu[HS + r * 132 + ww] =
                f2h2(fmaxf(acc[mi][ni][0] + c0, 0.f), fmaxf(acc[mi][ni][1] + c1, 0.f));
            smu[HS + (r + 8) * 132 + ww] =
                f2h2(fmaxf(acc[mi][ni][2] + c0, 0.f), fmaxf(acc[mi][ni][3] + c1, 0.f));
#pragma unroll
            for (int q = 0; q < 4; q++) acc[mi][ni][q] = 0.f;
        }
    }

    // ---- layer 2: K = 256 halves, A = HS resident; L2 chunk j -> buf j&3 ----
#pragma unroll 1
    for (int kc2 = 0; kc2 < 8; kc2++) {
        if (kc2 < 6) { stageW(w2t, kc2 + 2, (kc2 + 2) & 3); CP_COMMIT(); }
        if (kc2 < 6) CP_WAIT2(); else if (kc2 == 6) CP_WAIT1(); else CP_WAIT0();
        __syncthreads();
        do_chunk(offH, sb + (unsigned)(kc2 * 64),
                 offB, sb + (unsigned)(WB + (kc2 & 3) * 4096) * 4u, acc);
    }

    // ---- h2 (fp32 regs) + layer-3 partials; quad butterfly (xor1,xor2: fixed order) ----
    {
        float p[2][2][3];
#pragma unroll
        for (int mi = 0; mi < 2; mi++)
#pragma unroll
            for (int h = 0; h < 2; h++)
#pragma unroll
                for (int o = 0; o < 3; o++) p[mi][h][o] = 0.f;
#pragma unroll
        for (int ni = 0; ni < 8; ni++) {
            int n = wn * 64 + ni * 8 + 2 * (lane & 3);
            float c0 = smf[B2S + n], c1 = smf[B2S + n + 1];
#pragma unroll
            for (int mi = 0; mi < 2; mi++) {
                float v00 = fmaxf(acc[mi][ni][0] + c0, 0.f);
                float v01 = fmaxf(acc[mi][ni][1] + c1, 0.f);
                float v10 = fmaxf(acc[mi][ni][2] + c0, 0.f);
                float v11 = fmaxf(acc[mi][ni][3] + c1, 0.f);
#pragma unroll
                for (int o = 0; o < 3; o++) {
                    if (o >= nout) break;
                    float w0 = smf[W3S + n * nout + o];
                    float w1v = smf[W3S + (n + 1) * nout + o];
                    p[mi][0][o] = fmaf(v00, w0, fmaf(v01, w1v, p[mi][0][o]));
                    p[mi][1][o] = fmaf(v10, w0, fmaf(v11, w1v, p[mi][1][o]));
                }
            }
        }
#pragma unroll
        for (int mi = 0; mi < 2; mi++)
#pragma unroll
            for (int h = 0; h < 2; h++)
#pragma unroll
                for (int o = 0; o < 3; o++) {
                    if (o >= nout) break;
                    float v = p[mi][h][o];
                    v += __shfl_xor_sync(0xFFFFFFFFu, v, 1);
                    v += __shfl_xor_sync(0xFFFFFFFFu, v, 2);
                    p[mi][h][o] = v;
                }
        if ((lane & 3) == 0) {
#pragma unroll
            for (int mi = 0; mi < 2; mi++)
#pragma unroll
                for (int h = 0; h < 2; h++) {
                    int row = wm * 32 + mi * 16 + (lane >> 2) + 8 * h;
#pragma unroll
                    for (int o = 0; o < 3; o++) {
                        if (o >= nout) break;
                        smf[RED + (row * 4 + wn) * 3 + o] = p[mi][h][o];
                    }
                }
        }
    }
    __syncthreads();
    if (tid < nrows) {
        size_t orow = (size_t)rid[tid];
#pragma unroll
        for (int o = 0; o < 3; o++) {
            if (o >= nout) break;
            float s = b3[o];
#pragma unroll
            for (int g = 0; g < 4; g++) s += smf[RED + (tid * 4 + g) * 3 + o];
            if (sig) s = 1.f / (1.f + expf(-s));
            obase[orow * nout + o] = s;
        }
    }
}

// ---------------- launch ----------------
extern "C" void kernel_launch(void* const* d_in, const int* in_sizes, int n_in,
                              void* d_out, int out_size) {
    const float* embedding = (const float*)d_in[0];
    const float* speed     = (const float*)d_in[1];
    const int*   command   = (const int*)d_in[2];
    const float* sw1 = (const float*)d_in[3];
    const float* sb1 = (const float*)d_in[4];
    const float* sw2 = (const float*)d_in[5];
    const float* sb2 = (const float*)d_in[6];
    const float* bw1 = (const float*)d_in[7];
    const float* bb1 = (const float*)d_in[8];
    const float* bw2 = (const float*)d_in[9];
    const float* bb2 = (const float*)d_in[10];
    const float* bw3 = (const float*)d_in[11];
    const float* bb3 = (const float*)d_in[12];
    const float* ow1 = (const float*)d_in[13];
    const float* ob1 = (const float*)d_in[14];
    const float* ow2 = (const float*)d_in[15];
    const float* ob2 = (const float*)d_in[16];
    const float* ow3 = (const float*)d_in[17];
    const float* ob3 = (const float*)d_in[18];
    float* out = (float*)d_out;

    const int SMEM_EMB = EMB_WORDS * 4;   // 135,680 B
    const int SMEM_MLP = MLP_WORDS * 4;   // 177,664 B
    cudaFuncSetAttribute((const void*)k_emb,
                         cudaFuncAttributeMaxDynamicSharedMemorySize, SMEM_EMB);
    cudaFuncSetAttribute((const void*)k_mlp,
                         cudaFuncAttributeMaxDynamicSharedMemorySize, SMEM_MLP);

    k_cvtw<<<736, 256>>>(sw2, bw1, bw2, ow1, ow2, command);
    k_plan<<<1, 32>>>();
    k_scatter<<<BATCH / 512, 512>>>(command);
    k_emb<<<dim3(BATCH / 128, DD / 256), 512, SMEM_EMB>>>(embedding, speed, sw1, sb1, sb2);
    k_mlp<<<MAX_TILES + BATCH / TM, 512, SMEM_MLP>>>(bb1, bb2, bw3, bb3,
                                                     ob1, ob2, ow3, ob3, out);
}